// round 1
// baseline (speedup 1.0000x reference)
#include <cuda_runtime.h>
#include <math.h>

#define MAXN 100000
#define MAXE 1600000

// ---------------- scratch (device globals; no allocation allowed) ----------
__device__ float g_bufA[MAXN * 68];
__device__ float g_bufB[MAXN * 68];
__device__ float g_dinv[MAXN];
__device__ float g_csrw[MAXE];
__device__ int   g_cnt[MAXN];
__device__ int   g_fill[MAXN];
__device__ int   g_rowptr[MAXN + 1];
__device__ int   g_csr[MAXE];
__device__ int   g_bsum[128];

// ---------------- CSR build ------------------------------------------------
__global__ void k_zero_cnt(int* cnt, int n) {
    int i = blockIdx.x * blockDim.x + threadIdx.x;
    if (i < n) cnt[i] = 0;
}

__global__ void k_count(const int* __restrict__ dst, int E, int* __restrict__ cnt) {
    int e = blockIdx.x * blockDim.x + threadIdx.x;
    if (e < E) atomicAdd(&cnt[dst[e]], 1);
}

// per-1024-block inclusive scan; writes into rowptr+1, block totals to bsum
__global__ void k_scan_block(const int* __restrict__ cnt, int n,
                             int* __restrict__ incl, int* __restrict__ bsum) {
    __shared__ int sh[1024];
    int tid = threadIdx.x;
    int gid = blockIdx.x * 1024 + tid;
    int v = (gid < n) ? cnt[gid] : 0;
    sh[tid] = v;
    __syncthreads();
    for (int off = 1; off < 1024; off <<= 1) {
        int t = 0;
        if (tid >= off) t = sh[tid - off];
        __syncthreads();
        sh[tid] += t;
        __syncthreads();
    }
    if (gid < n) incl[gid] = sh[tid];
    if (tid == 1023) bsum[blockIdx.x] = sh[1023];
}

// exclusive scan of block sums (small: <=128 entries), in place
__global__ void k_scan_sums(int* bsum, int nb) {
    __shared__ int sh[128];
    int tid = threadIdx.x;
    if (tid < nb) sh[tid] = bsum[tid];
    __syncthreads();
    if (tid == 0) {
        int acc = 0;
        for (int i = 0; i < nb; i++) { int v = sh[i]; sh[i] = acc; acc += v; }
    }
    __syncthreads();
    if (tid < nb) bsum[tid] = sh[tid];
}

// rowptr[i+1] += offset of its scan block; rowptr[0]=0; dinv; fill=0
__global__ void k_finalize(const int* __restrict__ bsum, int* __restrict__ rowptr,
                           const int* __restrict__ cnt, float* __restrict__ dinv,
                           int* __restrict__ fill, int n) {
    int i = blockIdx.x * blockDim.x + threadIdx.x;
    if (i < n) {
        rowptr[i + 1] += bsum[i >> 10];
        dinv[i] = rsqrtf((float)(cnt[i] + 1));  // +1 = self loop
        fill[i] = 0;
        if (i == 0) rowptr[0] = 0;
    }
}

__global__ void k_fill(const int* __restrict__ src, const int* __restrict__ dst, int E,
                       const int* __restrict__ rowptr, int* __restrict__ fill,
                       int* __restrict__ csr, float* __restrict__ csrw,
                       const float* __restrict__ dinv) {
    int e = blockIdx.x * blockDim.x + threadIdx.x;
    if (e < E) {
        int d = dst[e];
        int p = atomicAdd(&fill[d], 1);
        int idx = rowptr[d] + p;
        int s = src[e];
        csr[idx] = s;
        csrw[idx] = dinv[s];
    }
}

// ---------------- GEMM: C[N,M] = A[N,K] * W[K,M] (+bias)(+relu) ------------
// 64x64 tile, 256 threads, 4x4 register tile per thread.
__global__ void k_sgemm(const float* __restrict__ A, int lda,
                        const float* __restrict__ W, int M,
                        const float* __restrict__ bias,
                        float* __restrict__ C, int ldc,
                        int N, int K, int relu) {
    __shared__ __align__(16) float sA[88 * 68];  // [k][row], padded row=68
    __shared__ __align__(16) float sW[88 * 64];  // [k][col]
    int tid = threadIdx.x;
    int r0 = blockIdx.x * 64;
    int c0 = blockIdx.y * 64;

    for (int i = tid; i < 64 * K; i += 256) {
        int r = i / K;
        int k = i - r * K;
        int gr = r0 + r;
        float v = 0.f;
        if (gr < N) v = A[(size_t)gr * lda + k];
        sA[k * 68 + r] = v;
    }
    for (int i = tid; i < K * 64; i += 256) {
        int k = i >> 6;
        int c = i & 63;
        int gc = c0 + c;
        float v = 0.f;
        if (gc < M) v = W[k * M + gc];
        sW[i] = v;
    }
    __syncthreads();

    int tx = tid & 15;   // row tile
    int ty = tid >> 4;   // col tile
    float acc[4][4];
#pragma unroll
    for (int m = 0; m < 4; m++)
#pragma unroll
        for (int n2 = 0; n2 < 4; n2++) acc[m][n2] = 0.f;

    for (int k = 0; k < K; k++) {
        float4 a = *(const float4*)&sA[k * 68 + 4 * tx];
        float4 w = *(const float4*)&sW[k * 64 + 4 * ty];
        acc[0][0] += a.x * w.x; acc[0][1] += a.x * w.y; acc[0][2] += a.x * w.z; acc[0][3] += a.x * w.w;
        acc[1][0] += a.y * w.x; acc[1][1] += a.y * w.y; acc[1][2] += a.y * w.z; acc[1][3] += a.y * w.w;
        acc[2][0] += a.z * w.x; acc[2][1] += a.z * w.y; acc[2][2] += a.z * w.z; acc[2][3] += a.z * w.w;
        acc[3][0] += a.w * w.x; acc[3][1] += a.w * w.y; acc[3][2] += a.w * w.z; acc[3][3] += a.w * w.w;
    }

    int gc0 = c0 + 4 * ty;
#pragma unroll
    for (int m = 0; m < 4; m++) {
        int gr = r0 + 4 * tx + m;
        if (gr >= N) continue;
        if (gc0 + 3 < M) {
            float4 o;
            float v0 = acc[m][0], v1 = acc[m][1], v2 = acc[m][2], v3 = acc[m][3];
            if (bias) { v0 += bias[gc0]; v1 += bias[gc0 + 1]; v2 += bias[gc0 + 2]; v3 += bias[gc0 + 3]; }
            if (relu) { v0 = fmaxf(v0, 0.f); v1 = fmaxf(v1, 0.f); v2 = fmaxf(v2, 0.f); v3 = fmaxf(v3, 0.f); }
            o.x = v0; o.y = v1; o.z = v2; o.w = v3;
            *(float4*)&C[(size_t)gr * ldc + gc0] = o;
        } else {
#pragma unroll
            for (int n2 = 0; n2 < 4; n2++) {
                int gc = gc0 + n2;
                if (gc < M) {
                    float v = acc[m][n2];
                    if (bias) v += bias[gc];
                    if (relu) v = fmaxf(v, 0.f);
                    C[(size_t)gr * ldc + gc] = v;
                }
            }
        }
    }
}

// ---------------- aggregation: o[i] = dinv_i*(sum_in dinv_s*t[s] + dinv_i*t[i]) + b
// warp per node, dst-centric (atomic-free). NC = number of 32-wide col chunks.
template <int NC>
__global__ void k_agg(const float* __restrict__ t, float* __restrict__ o,
                      const int* __restrict__ rowptr, const int* __restrict__ csr,
                      const float* __restrict__ csrw, const float* __restrict__ dinv,
                      const float* __restrict__ bias, int d, int S, int relu, int N) {
    int node = (blockIdx.x * blockDim.x + threadIdx.x) >> 5;
    int lane = threadIdx.x & 31;
    if (node >= N) return;
    int beg = rowptr[node];
    int end = rowptr[node + 1];

    float acc[NC];
#pragma unroll
    for (int c = 0; c < NC; c++) acc[c] = 0.f;

    int j = beg;
    for (; j + 2 <= end; j += 2) {
        int s0 = __ldg(&csr[j]);
        int s1 = __ldg(&csr[j + 1]);
        float w0 = __ldg(&csrw[j]);
        float w1 = __ldg(&csrw[j + 1]);
        const float* r0 = t + (size_t)s0 * S;
        const float* r1 = t + (size_t)s1 * S;
#pragma unroll
        for (int c = 0; c < NC; c++) {
            int col = c * 32 + lane;
            if (col < d) {
                acc[c] += w0 * __ldg(&r0[col]);
                acc[c] += w1 * __ldg(&r1[col]);
            }
        }
    }
    if (j < end) {
        int s0 = __ldg(&csr[j]);
        float w0 = __ldg(&csrw[j]);
        const float* r0 = t + (size_t)s0 * S;
#pragma unroll
        for (int c = 0; c < NC; c++) {
            int col = c * 32 + lane;
            if (col < d) acc[c] += w0 * __ldg(&r0[col]);
        }
    }

    float di = dinv[node];
    const float* ri = t + (size_t)node * S;
#pragma unroll
    for (int c = 0; c < NC; c++) {
        int col = c * 32 + lane;
        if (col < d) {
            float v = di * (acc[c] + di * ri[col]);
            if (bias) v += bias[col];
            if (relu) v = fmaxf(v, 0.f);
            o[(size_t)node * S + col] = v;
        }
    }
}

// ---------------- launch ----------------------------------------------------
extern "C" void kernel_launch(void* const* d_in, const int* in_sizes, int n_in,
                              void* d_out, int out_size) {
    const float* x  = (const float*)d_in[0];
    const float* W1 = (const float*)d_in[1];
    const float* b1 = (const float*)d_in[2];
    const float* W2 = (const float*)d_in[3];
    const float* b2 = (const float*)d_in[4];
    const float* W3 = (const float*)d_in[5];
    const float* b3 = (const float*)d_in[6];
    const float* W4 = (const float*)d_in[7];
    const float* b4 = (const float*)d_in[8];
    const int*   ei = (const int*)d_in[9];

    int N = in_sizes[0] / 88;
    int E = in_sizes[9] / 2;
    const int* src = ei;
    const int* dst = ei + E;
    float* out = (float*)d_out;

    float *bufA, *bufB, *dinv, *csrw;
    int *cnt, *fill, *rowptr, *csr, *bsum;
    cudaGetSymbolAddress((void**)&bufA, g_bufA);
    cudaGetSymbolAddress((void**)&bufB, g_bufB);
    cudaGetSymbolAddress((void**)&dinv, g_dinv);
    cudaGetSymbolAddress((void**)&csrw, g_csrw);
    cudaGetSymbolAddress((void**)&cnt, g_cnt);
    cudaGetSymbolAddress((void**)&fill, g_fill);
    cudaGetSymbolAddress((void**)&rowptr, g_rowptr);
    cudaGetSymbolAddress((void**)&csr, g_csr);
    cudaGetSymbolAddress((void**)&bsum, g_bsum);

    // ---- CSR build ----
    k_zero_cnt<<<(N + 255) / 256, 256>>>(cnt, N);
    k_count<<<(E + 255) / 256, 256>>>(dst, E, cnt);
    int nb = (N + 1023) / 1024;
    k_scan_block<<<nb, 1024>>>(cnt, N, rowptr + 1, bsum);
    k_scan_sums<<<1, 128>>>(bsum, nb);
    k_finalize<<<(N + 255) / 256, 256>>>(bsum, rowptr, cnt, dinv, fill, N);
    k_fill<<<(E + 255) / 256, 256>>>(src, dst, E, rowptr, fill, csr, csrw, dinv);

    int aggBlocks = (N * 32 + 255) / 256;

    // L1: t = x @ W1 (88->65); h1 = relu(A t + b1)     [bufA -> bufB, S=68]
    {
        dim3 g((N + 63) / 64, (65 + 63) / 64);
        k_sgemm<<<g, 256>>>(x, 88, W1, 65, nullptr, bufA, 68, N, 88, 0);
        k_agg<3><<<aggBlocks, 256>>>(bufA, bufB, rowptr, csr, csrw, dinv, b1, 65, 68, 1, N);
    }
    // L2: t = h1 @ W2 (65->50); h2 = A t + b2          [bufA -> bufB, S=52]
    {
        dim3 g((N + 63) / 64, (50 + 63) / 64);
        k_sgemm<<<g, 256>>>(bufB, 68, W2, 50, nullptr, bufA, 52, N, 65, 0);
        k_agg<2><<<aggBlocks, 256>>>(bufA, bufB, rowptr, csr, csrw, dinv, b2, 50, 52, 0, N);
    }
    // L3: a = A h2 (50); h3 = relu(a @ W3 + b3)        [bufB -> bufA -> bufB, S=68]
    {
        k_agg<2><<<aggBlocks, 256>>>(bufB, bufA, rowptr, csr, csrw, dinv, nullptr, 50, 52, 0, N);
        dim3 g((N + 63) / 64, (65 + 63) / 64);
        k_sgemm<<<g, 256>>>(bufA, 52, W3, 65, b3, bufB, 68, N, 50, 1);
    }
    // L4: a = A h3 (65); out = a @ W4 + b4             [bufB -> bufA -> d_out]
    {
        k_agg<3><<<aggBlocks, 256>>>(bufB, bufA, rowptr, csr, csrw, dinv, nullptr, 65, 68, 0, N);
        dim3 g((N + 63) / 64, (88 + 63) / 64);
        k_sgemm<<<g, 256>>>(bufA, 68, W4, 88, b4, out, 88, N, 65, 0);
    }
}

// round 3
// speedup vs baseline: 1.1229x; 1.1229x over previous
#include <cuda_runtime.h>
#include <math.h>

#define MAXN 100000
#define MAXE 1600000

// ---------------- scratch (device globals; no allocation allowed) ----------
__device__ float g_bufA[MAXN * 68];
__device__ float g_bufB[MAXN * 68];
__device__ float g_dinv[MAXN];
__device__ int   g_cnt[MAXN];
__device__ int   g_fill[MAXN];
__device__ int   g_rowptr[MAXN + 1];
__device__ int   g_csr[MAXE];
__device__ int   g_bsum[128];

// ---------------- CSR build ------------------------------------------------
__global__ void k_count(const int* __restrict__ dst, int E, int* __restrict__ cnt) {
    int e = blockIdx.x * blockDim.x + threadIdx.x;
    if (e < E) atomicAdd(&cnt[dst[e]], 1);
}

// per-1024-block inclusive scan; writes into rowptr+1, block totals to bsum
__global__ void k_scan_block(const int* __restrict__ cnt, int n,
                             int* __restrict__ incl, int* __restrict__ bsum) {
    __shared__ int sh[1024];
    int tid = threadIdx.x;
    int gid = blockIdx.x * 1024 + tid;
    int v = (gid < n) ? cnt[gid] : 0;
    sh[tid] = v;
    __syncthreads();
    for (int off = 1; off < 1024; off <<= 1) {
        int t = 0;
        if (tid >= off) t = sh[tid - off];
        __syncthreads();
        sh[tid] += t;
        __syncthreads();
    }
    if (gid < n) incl[gid] = sh[tid];
    if (tid == 1023) bsum[blockIdx.x] = sh[1023];
}

// exclusive scan of block sums (<=128 entries), parallel, in place
__global__ void k_scan_sums(int* bsum, int nb) {
    __shared__ int sh[128];
    int tid = threadIdx.x;
    int v = (tid < nb) ? bsum[tid] : 0;
    sh[tid] = v;
    __syncthreads();
    for (int off = 1; off < 128; off <<= 1) {
        int t = 0;
        if (tid >= off) t = sh[tid - off];
        __syncthreads();
        sh[tid] += t;
        __syncthreads();
    }
    if (tid < nb) bsum[tid] = (tid == 0) ? 0 : sh[tid - 1];
}

// rowptr[i+1] += offset of its scan block; rowptr[0]=0; dinv; fill=0
__global__ void k_finalize(const int* __restrict__ bsum, int* __restrict__ rowptr,
                           const int* __restrict__ cnt, float* __restrict__ dinv,
                           int* __restrict__ fill, int n) {
    int i = blockIdx.x * blockDim.x + threadIdx.x;
    if (i < n) {
        rowptr[i + 1] += bsum[i >> 10];
        dinv[i] = rsqrtf((float)(cnt[i] + 1));  // +1 = self loop
        fill[i] = 0;
        if (i == 0) rowptr[0] = 0;
    }
}

__global__ void k_fill(const int* __restrict__ src, const int* __restrict__ dst, int E,
                       const int* __restrict__ rowptr, int* __restrict__ fill,
                       int* __restrict__ csr) {
    int e = blockIdx.x * blockDim.x + threadIdx.x;
    if (e < E) {
        int d = dst[e];
        int p = atomicAdd(&fill[d], 1);
        csr[rowptr[d] + p] = src[e];
    }
}

// ---------------- GEMM: C[N,M] = A[N,K] * W[K,M] (+bias)(+relu)(xdinv) -----
// 64-row tile, exact col coverage MR (M rounded to x4). blockDim = (8, MR/4).
// Per-thread register tile: 8 rows x 4 cols.
template <int K, int MR>
__global__ void k_sgemm(const float* __restrict__ A, int lda,
                        const float* __restrict__ W, int M,
                        const float* __restrict__ bias,
                        const float* __restrict__ dinv,   // row scale or nullptr
                        float* __restrict__ C, int ldc,
                        int N, int relu) {
    __shared__ __align__(16) float sA[K * 68];  // [k][row], 64 rows padded to 68
    __shared__ __align__(16) float sW[K * MR];  // [k][col]
    const int nth = 8 * (MR / 4);
    int tx = threadIdx.x;        // 0..7
    int ty = threadIdx.y;        // 0..MR/4-1
    int tid = ty * 8 + tx;
    int r0 = blockIdx.x * 64;

    for (int i = tid; i < 64 * K; i += nth) {
        int r = i / K;
        int k = i - r * K;
        int gr = r0 + r;
        sA[k * 68 + r] = (gr < N) ? A[(size_t)gr * lda + k] : 0.f;
    }
    for (int i = tid; i < K * MR; i += nth) {
        int k = i / MR;
        int c = i - k * MR;
        sW[i] = (c < M) ? W[k * M + c] : 0.f;
    }
    __syncthreads();

    float acc[8][4];
#pragma unroll
    for (int m = 0; m < 8; m++)
#pragma unroll
        for (int n2 = 0; n2 < 4; n2++) acc[m][n2] = 0.f;

#pragma unroll 5
    for (int k = 0; k < K; k++) {
        float4 a0 = *(const float4*)&sA[k * 68 + 8 * tx];
        float4 a1 = *(const float4*)&sA[k * 68 + 8 * tx + 4];
        float4 w  = *(const float4*)&sW[k * MR + 4 * ty];
        float av[8] = {a0.x, a0.y, a0.z, a0.w, a1.x, a1.y, a1.z, a1.w};
#pragma unroll
        for (int m = 0; m < 8; m++) {
            acc[m][0] += av[m] * w.x;
            acc[m][1] += av[m] * w.y;
            acc[m][2] += av[m] * w.z;
            acc[m][3] += av[m] * w.w;
        }
    }

    int gc0 = 4 * ty;
    float bv[4];
#pragma unroll
    for (int n2 = 0; n2 < 4; n2++)
        bv[n2] = (bias && gc0 + n2 < M) ? bias[gc0 + n2] : 0.f;

#pragma unroll
    for (int m = 0; m < 8; m++) {
        int gr = r0 + 8 * tx + m;
        if (gr >= N) continue;
        float sc = dinv ? dinv[gr] : 1.f;
        float v0 = acc[m][0] + bv[0];
        float v1 = acc[m][1] + bv[1];
        float v2 = acc[m][2] + bv[2];
        float v3 = acc[m][3] + bv[3];
        if (relu) {
            v0 = fmaxf(v0, 0.f); v1 = fmaxf(v1, 0.f);
            v2 = fmaxf(v2, 0.f); v3 = fmaxf(v3, 0.f);
        }
        v0 *= sc; v1 *= sc; v2 *= sc; v3 *= sc;
        if (gc0 + 3 < M) {
            float4 o = {v0, v1, v2, v3};
            *(float4*)&C[(size_t)gr * ldc + gc0] = o;
        } else {
            if (gc0 + 0 < M) C[(size_t)gr * ldc + gc0 + 0] = v0;
            if (gc0 + 1 < M) C[(size_t)gr * ldc + gc0 + 1] = v1;
            if (gc0 + 2 < M) C[(size_t)gr * ldc + gc0 + 2] = v2;
            if (gc0 + 3 < M) C[(size_t)gr * ldc + gc0 + 3] = v3;
        }
    }
}

// ---------------- aggregation: pure gather-sum (weights folded into rows) --
// o[i] = epi( dinv_i * (sum_{s in N(i)} t[s] + t[i]) )
// epi: (+bias) (relu) (xdinv_i again if post2)
template <int NC>
__global__ void k_agg(const float* __restrict__ t, float* __restrict__ o,
                      const int* __restrict__ rowptr, const int* __restrict__ csr,
                      const float* __restrict__ dinv,
                      const float* __restrict__ bias, int d, int Sin, int Sout,
                      int relu, int post2, int N) {
    int node = (blockIdx.x * blockDim.x + threadIdx.x) >> 5;
    int lane = threadIdx.x & 31;
    if (node >= N) return;
    int beg = rowptr[node];
    int end = rowptr[node + 1];

    float acc[NC];
#pragma unroll
    for (int c = 0; c < NC; c++) acc[c] = 0.f;

    int j = beg;
    for (; j + 4 <= end; j += 4) {
        int s0 = __ldg(&csr[j]);
        int s1 = __ldg(&csr[j + 1]);
        int s2 = __ldg(&csr[j + 2]);
        int s3 = __ldg(&csr[j + 3]);
        const float* r0 = t + (size_t)s0 * Sin;
        const float* r1 = t + (size_t)s1 * Sin;
        const float* r2 = t + (size_t)s2 * Sin;
        const float* r3 = t + (size_t)s3 * Sin;
#pragma unroll
        for (int c = 0; c < NC; c++) {
            int col = c * 32 + lane;
            if (col < d) {
                float v0 = __ldg(&r0[col]);
                float v1 = __ldg(&r1[col]);
                float v2 = __ldg(&r2[col]);
                float v3 = __ldg(&r3[col]);
                acc[c] += (v0 + v1) + (v2 + v3);
            }
        }
    }
    for (; j < end; j++) {
        int s0 = __ldg(&csr[j]);
        const float* r0 = t + (size_t)s0 * Sin;
#pragma unroll
        for (int c = 0; c < NC; c++) {
            int col = c * 32 + lane;
            if (col < d) acc[c] += __ldg(&r0[col]);
        }
    }

    float di = dinv[node];
    const float* ri = t + (size_t)node * Sin;
#pragma unroll
    for (int c = 0; c < NC; c++) {
        int col = c * 32 + lane;
        if (col < d) {
            float v = (acc[c] + ri[col]) * di;   // self-loop row already carries dinv_i
            if (bias) v += bias[col];
            if (relu) v = fmaxf(v, 0.f);
            if (post2) v *= di;
            o[(size_t)node * Sout + col] = v;
        }
    }
}

// ---------------- launch ----------------------------------------------------
extern "C" void kernel_launch(void* const* d_in, const int* in_sizes, int n_in,
                              void* d_out, int out_size) {
    const float* x  = (const float*)d_in[0];
    const float* W1 = (const float*)d_in[1];
    const float* b1 = (const float*)d_in[2];
    const float* W2 = (const float*)d_in[3];
    const float* b2 = (const float*)d_in[4];
    const float* W3 = (const float*)d_in[5];
    const float* b3 = (const float*)d_in[6];
    const float* W4 = (const float*)d_in[7];
    const float* b4 = (const float*)d_in[8];
    const int*   ei = (const int*)d_in[9];

    int N = in_sizes[0] / 88;
    int E = in_sizes[9] / 2;
    const int* src = ei;
    const int* dst = ei + E;
    float* out = (float*)d_out;

    float *bufA, *bufB, *dinv;
    int *cnt, *fill, *rowptr, *csr, *bsum;
    cudaGetSymbolAddress((void**)&bufA, g_bufA);
    cudaGetSymbolAddress((void**)&bufB, g_bufB);
    cudaGetSymbolAddress((void**)&dinv, g_dinv);
    cudaGetSymbolAddress((void**)&cnt, g_cnt);
    cudaGetSymbolAddress((void**)&fill, g_fill);
    cudaGetSymbolAddress((void**)&rowptr, g_rowptr);
    cudaGetSymbolAddress((void**)&csr, g_csr);
    cudaGetSymbolAddress((void**)&bsum, g_bsum);

    // ---- CSR build (atomic histogram + two-level scan + fill) ----
    cudaMemsetAsync(cnt, 0, (size_t)N * sizeof(int));
    k_count<<<(E + 255) / 256, 256>>>(dst, E, cnt);
    int nb = (N + 1023) / 1024;
    k_scan_block<<<nb, 1024>>>(cnt, N, rowptr + 1, bsum);
    k_scan_sums<<<1, 128>>>(bsum, nb);
    k_finalize<<<(N + 255) / 256, 256>>>(bsum, rowptr, cnt, dinv, fill, N);
    k_fill<<<(E + 255) / 256, 256>>>(src, dst, E, rowptr, fill, csr);

    int aggBlocks = (N * 32 + 255) / 256;
    int gemmBlocks = (N + 63) / 64;

    // L1: t1 = (x @ W1) o dinv ; h1 = relu(dinv * sum t1 + b1)
    k_sgemm<88, 68><<<gemmBlocks, dim3(8, 17)>>>(x, 88, W1, 65, nullptr, dinv, bufA, 68, N, 0);
    k_agg<3><<<aggBlocks, 256>>>(bufA, bufB, rowptr, csr, dinv, b1, 65, 68, 68, 1, 0, N);

    // L2: t2 = (h1 @ W2) o dinv ; h2' = dinv * (dinv * sum t2 + b2)
    k_sgemm<65, 52><<<gemmBlocks, dim3(8, 13)>>>(bufB, 68, W2, 50, nullptr, dinv, bufA, 52, N, 0);
    k_agg<2><<<aggBlocks, 256>>>(bufA, bufB, rowptr, csr, dinv, b2, 50, 52, 52, 0, 1, N);

    // L3: a3 = dinv * sum h2' ; h3' = dinv o relu(a3 @ W3 + b3)
    k_agg<2><<<aggBlocks, 256>>>(bufB, bufA, rowptr, csr, dinv, nullptr, 50, 52, 52, 0, 0, N);
    k_sgemm<50, 68><<<gemmBlocks, dim3(8, 17)>>>(bufA, 52, W3, 65, b3, dinv, bufB, 68, N, 1);

    // L4: a4 = dinv * sum h3' ; out = a4 @ W4 + b4
    k_agg<3><<<aggBlocks, 256>>>(bufB, bufA, rowptr, csr, dinv, nullptr, 65, 68, 68, 0, 0, N);
    k_sgemm<65, 88><<<gemmBlocks, dim3(8, 22)>>>(bufA, 68, W4, 88, b4, nullptr, out, 88, N, 0);
}

// round 4
// speedup vs baseline: 1.1588x; 1.0319x over previous
#include <cuda_runtime.h>
#include <cuda_fp16.h>
#include <math.h>

#define MAXN 100000
#define MAXE 1600000
#define STR  68          // uniform row stride (elements)
#define STRH2 (STR / 2)  // stride in half2

// ---------------- scratch (device globals; no allocation allowed) ----------
__device__ __half g_bufHa[MAXN * STR];   // fp16 feature rows (gather source)
__device__ __half g_bufHb[MAXN * STR];   // fp16 feature rows (gather source)
__device__ float  g_bufF[MAXN * STR];    // fp32 rows (GEMM input)
__device__ float  g_dinv[MAXN];
__device__ int    g_cnt[MAXN];
__device__ int    g_fill[MAXN];
__device__ int    g_rowptr[MAXN + 1];
__device__ int    g_csr[MAXE];
__device__ int    g_bsum[128];

// ---------------- CSR build ------------------------------------------------
__global__ void k_count(const int* __restrict__ dst, int E, int* __restrict__ cnt) {
    int e = blockIdx.x * blockDim.x + threadIdx.x;
    if (e < E) atomicAdd(&cnt[dst[e]], 1);
}

__global__ void k_scan_block(const int* __restrict__ cnt, int n,
                             int* __restrict__ incl, int* __restrict__ bsum) {
    __shared__ int sh[1024];
    int tid = threadIdx.x;
    int gid = blockIdx.x * 1024 + tid;
    int v = (gid < n) ? cnt[gid] : 0;
    sh[tid] = v;
    __syncthreads();
    for (int off = 1; off < 1024; off <<= 1) {
        int t = 0;
        if (tid >= off) t = sh[tid - off];
        __syncthreads();
        sh[tid] += t;
        __syncthreads();
    }
    if (gid < n) incl[gid] = sh[tid];
    if (tid == 1023) bsum[blockIdx.x] = sh[1023];
}

__global__ void k_scan_sums(int* bsum, int nb) {
    __shared__ int sh[128];
    int tid = threadIdx.x;
    int v = (tid < nb) ? bsum[tid] : 0;
    sh[tid] = v;
    __syncthreads();
    for (int off = 1; off < 128; off <<= 1) {
        int t = 0;
        if (tid >= off) t = sh[tid - off];
        __syncthreads();
        sh[tid] += t;
        __syncthreads();
    }
    if (tid < nb) bsum[tid] = (tid == 0) ? 0 : sh[tid - 1];
}

__global__ void k_finalize(const int* __restrict__ bsum, int* __restrict__ rowptr,
                           const int* __restrict__ cnt, float* __restrict__ dinv,
                           int* __restrict__ fill, int n) {
    int i = blockIdx.x * blockDim.x + threadIdx.x;
    if (i < n) {
        rowptr[i + 1] += bsum[i >> 10];
        dinv[i] = rsqrtf((float)(cnt[i] + 1));  // +1 = self loop
        fill[i] = 0;
        if (i == 0) rowptr[0] = 0;
    }
}

__global__ void k_fill(const int* __restrict__ src, const int* __restrict__ dst, int E,
                       const int* __restrict__ rowptr, int* __restrict__ fill,
                       int* __restrict__ csr) {
    int e = blockIdx.x * blockDim.x + threadIdx.x;
    if (e < E) {
        int d = dst[e];
        int p = atomicAdd(&fill[d], 1);
        csr[rowptr[d] + p] = src[e];
    }
}

// ---------------- GEMM: C[N,M] = A[N,K] * W[K,M] (+bias)(relu)(xdinv) ------
// 64-row tile, exact col coverage MR (M rounded up to x4). blockDim=(8, MR/4).
// Cols in [M, MR) are written as ZERO (padding for fp16 gather consumers).
template <int K, int MR, bool OUT_HALF>
__global__ void k_sgemm(const float* __restrict__ A, int lda,
                        const float* __restrict__ W, int M,
                        const float* __restrict__ bias,
                        const float* __restrict__ dinv,   // row scale or nullptr
                        void* __restrict__ Cv, int ldc,
                        int N, int relu) {
    __shared__ __align__(16) float sA[K * 68];
    __shared__ __align__(16) float sW[K * MR];
    const int nth = 8 * (MR / 4);
    int tx = threadIdx.x;
    int ty = threadIdx.y;
    int tid = ty * 8 + tx;
    int r0 = blockIdx.x * 64;

    for (int i = tid; i < 64 * K; i += nth) {
        int r = i / K;
        int k = i - r * K;
        int gr = r0 + r;
        sA[k * 68 + r] = (gr < N) ? A[(size_t)gr * lda + k] : 0.f;
    }
    for (int i = tid; i < K * MR; i += nth) {
        int k = i / MR;
        int c = i - k * MR;
        sW[i] = (c < M) ? W[k * M + c] : 0.f;
    }
    __syncthreads();

    float acc[8][4];
#pragma unroll
    for (int m = 0; m < 8; m++)
#pragma unroll
        for (int n2 = 0; n2 < 4; n2++) acc[m][n2] = 0.f;

#pragma unroll 5
    for (int k = 0; k < K; k++) {
        float4 a0 = *(const float4*)&sA[k * 68 + 8 * tx];
        float4 a1 = *(const float4*)&sA[k * 68 + 8 * tx + 4];
        float4 w  = *(const float4*)&sW[k * MR + 4 * ty];
        float av[8] = {a0.x, a0.y, a0.z, a0.w, a1.x, a1.y, a1.z, a1.w};
#pragma unroll
        for (int m = 0; m < 8; m++) {
            acc[m][0] += av[m] * w.x;
            acc[m][1] += av[m] * w.y;
            acc[m][2] += av[m] * w.z;
            acc[m][3] += av[m] * w.w;
        }
    }

    int gc0 = 4 * ty;
    float bv[4];
#pragma unroll
    for (int n2 = 0; n2 < 4; n2++)
        bv[n2] = (bias && gc0 + n2 < M) ? bias[gc0 + n2] : 0.f;

#pragma unroll
    for (int m = 0; m < 8; m++) {
        int gr = r0 + 8 * tx + m;
        if (gr >= N) continue;
        float sc = dinv ? dinv[gr] : 1.f;
        float v[4];
#pragma unroll
        for (int n2 = 0; n2 < 4; n2++) {
            float t = acc[m][n2] + bv[n2];
            if (relu) t = fmaxf(t, 0.f);
            t *= sc;
            v[n2] = (gc0 + n2 < M) ? t : 0.f;   // zero-pad tail cols
        }
        if (OUT_HALF) {
            __half2* Ch = (__half2*)((__half*)Cv + (size_t)gr * ldc + gc0);
            Ch[0] = __floats2half2_rn(v[0], v[1]);
            Ch[1] = __floats2half2_rn(v[2], v[3]);
        } else {
            float4 o = {v[0], v[1], v[2], v[3]};
            *(float4*)((float*)Cv + (size_t)gr * ldc + gc0) = o;
        }
    }
}

// ---------------- aggregation (fp16 gather, fp32 accumulate) ---------------
// o[i] = epi( dinv_i * (sum_{s in N(i)} t[s] + t[i]) ), rows of t pre-scaled.
// epi: (+bias) (relu) (xdinv_i if post2). D2 = half2 count per row.
template <int D2, bool OUT_HALF>
__global__ void k_agg(const __half2* __restrict__ t,
                      void* __restrict__ o,
                      const int* __restrict__ rowptr, const int* __restrict__ csr,
                      const float* __restrict__ dinv,
                      const float* __restrict__ bias, int d,
                      int relu, int post2, int N) {
    constexpr int NCH = (D2 + 31) / 32;
    int node = (blockIdx.x * blockDim.x + threadIdx.x) >> 5;
    int lane = threadIdx.x & 31;
    if (node >= N) return;
    int beg = rowptr[node];
    int end = rowptr[node + 1];

    float2 acc[NCH];
#pragma unroll
    for (int c = 0; c < NCH; c++) acc[c] = make_float2(0.f, 0.f);

    int j = beg;
    for (; j + 4 <= end; j += 4) {
        int s0 = __ldg(&csr[j]);
        int s1 = __ldg(&csr[j + 1]);
        int s2 = __ldg(&csr[j + 2]);
        int s3 = __ldg(&csr[j + 3]);
        const __half2* r0 = t + (size_t)s0 * STRH2;
        const __half2* r1 = t + (size_t)s1 * STRH2;
        const __half2* r2 = t + (size_t)s2 * STRH2;
        const __half2* r3 = t + (size_t)s3 * STRH2;
#pragma unroll
        for (int c = 0; c < NCH; c++) {
            int idx = c * 32 + lane;
            if (idx < D2) {
                float2 f0 = __half22float2(__ldg(&r0[idx]));
                float2 f1 = __half22float2(__ldg(&r1[idx]));
                float2 f2 = __half22float2(__ldg(&r2[idx]));
                float2 f3 = __half22float2(__ldg(&r3[idx]));
                acc[c].x += (f0.x + f1.x) + (f2.x + f3.x);
                acc[c].y += (f0.y + f1.y) + (f2.y + f3.y);
            }
        }
    }
    for (; j < end; j++) {
        int s0 = __ldg(&csr[j]);
        const __half2* r0 = t + (size_t)s0 * STRH2;
#pragma unroll
        for (int c = 0; c < NCH; c++) {
            int idx = c * 32 + lane;
            if (idx < D2) {
                float2 f0 = __half22float2(__ldg(&r0[idx]));
                acc[c].x += f0.x;
                acc[c].y += f0.y;
            }
        }
    }

    // self loop (row already carries dinv_i)
    {
        const __half2* ri = t + (size_t)node * STRH2;
#pragma unroll
        for (int c = 0; c < NCH; c++) {
            int idx = c * 32 + lane;
            if (idx < D2) {
                float2 f = __half22float2(__ldg(&ri[idx]));
                acc[c].x += f.x;
                acc[c].y += f.y;
            }
        }
    }

    float di = dinv[node];
#pragma unroll
    for (int c = 0; c < NCH; c++) {
        int idx = c * 32 + lane;
        if (idx >= D2) continue;
        int col0 = 2 * idx, col1 = 2 * idx + 1;
        float vx = acc[c].x * di;
        float vy = acc[c].y * di;
        if (bias) {
            vx += (col0 < d) ? bias[col0] : 0.f;
            vy += (col1 < d) ? bias[col1] : 0.f;
        }
        if (relu) { vx = fmaxf(vx, 0.f); vy = fmaxf(vy, 0.f); }
        if (post2) { vx *= di; vy *= di; }
        if (col0 >= d) vx = 0.f;
        if (col1 >= d) vy = 0.f;
        if (OUT_HALF) {
            ((__half2*)o)[(size_t)node * STRH2 + idx] = __floats2half2_rn(vx, vy);
        } else {
            ((float2*)o)[(size_t)node * STRH2 + idx] = make_float2(vx, vy);
        }
    }
}

// ---------------- launch ----------------------------------------------------
extern "C" void kernel_launch(void* const* d_in, const int* in_sizes, int n_in,
                              void* d_out, int out_size) {
    const float* x  = (const float*)d_in[0];
    const float* W1 = (const float*)d_in[1];
    const float* b1 = (const float*)d_in[2];
    const float* W2 = (const float*)d_in[3];
    const float* b2 = (const float*)d_in[4];
    const float* W3 = (const float*)d_in[5];
    const float* b3 = (const float*)d_in[6];
    const float* W4 = (const float*)d_in[7];
    const float* b4 = (const float*)d_in[8];
    const int*   ei = (const int*)d_in[9];

    int N = in_sizes[0] / 88;
    int E = in_sizes[9] / 2;
    const int* src = ei;
    const int* dst = ei + E;
    float* out = (float*)d_out;

    __half *Ha, *Hb;
    float *F, *dinv;
    int *cnt, *fill, *rowptr, *csr, *bsum;
    cudaGetSymbolAddress((void**)&Ha, g_bufHa);
    cudaGetSymbolAddress((void**)&Hb, g_bufHb);
    cudaGetSymbolAddress((void**)&F, g_bufF);
    cudaGetSymbolAddress((void**)&dinv, g_dinv);
    cudaGetSymbolAddress((void**)&cnt, g_cnt);
    cudaGetSymbolAddress((void**)&fill, g_fill);
    cudaGetSymbolAddress((void**)&rowptr, g_rowptr);
    cudaGetSymbolAddress((void**)&csr, g_csr);
    cudaGetSymbolAddress((void**)&bsum, g_bsum);

    // ---- CSR build ----
    cudaMemsetAsync(cnt, 0, (size_t)N * sizeof(int));
    k_count<<<(E + 255) / 256, 256>>>(dst, E, cnt);
    int nb = (N + 1023) / 1024;
    k_scan_block<<<nb, 1024>>>(cnt, N, rowptr + 1, bsum);
    k_scan_sums<<<1, 128>>>(bsum, nb);
    k_finalize<<<(N + 255) / 256, 256>>>(bsum, rowptr, cnt, dinv, fill, N);
    k_fill<<<(E + 255) / 256, 256>>>(src, dst, E, rowptr, fill, csr);

    int aggBlocks = (N * 32 + 255) / 256;
    int gemmBlocks = (N + 63) / 64;

    // L1: t1 = dinv o (x@W1) -> Ha(fp16);  h1 = relu(di*S + b1) -> F(fp32)
    k_sgemm<88, 68, true><<<gemmBlocks, dim3(8, 17)>>>(x, 88, W1, 65, nullptr, dinv, Ha, STR, N, 0);
    k_agg<33, false><<<aggBlocks, 256>>>((const __half2*)Ha, F, rowptr, csr, dinv, b1, 65, 1, 0, N);

    // L2: t2 = dinv o (h1@W2) -> Ha(fp16); h2' = dinv o (di*S + b2) -> Hb(fp16)
    k_sgemm<65, 52, true><<<gemmBlocks, dim3(8, 13)>>>(F, STR, W2, 50, nullptr, dinv, Ha, STR, N, 0);
    k_agg<25, true><<<aggBlocks, 256>>>((const __half2*)Ha, Hb, rowptr, csr, dinv, b2, 50, 0, 1, N);

    // L3: a3 = di*S(Hb) -> F(fp32);  t3 = dinv o relu(a3@W3 + b3) -> Ha(fp16)
    k_agg<25, false><<<aggBlocks, 256>>>((const __half2*)Hb, F, rowptr, csr, dinv, nullptr, 50, 0, 0, N);
    k_sgemm<50, 68, true><<<gemmBlocks, dim3(8, 17)>>>(F, STR, W3, 65, b3, dinv, Ha, STR, N, 1);

    // L4: a4 = di*S(Ha) -> F(fp32);  out = a4@W4 + b4 -> d_out(fp32)
    k_agg<33, false><<<aggBlocks, 256>>>((const __half2*)Ha, F, rowptr, csr, dinv, nullptr, 65, 0, 0, N);
    k_sgemm<65, 88, false><<<gemmBlocks, dim3(8, 22)>>>(F, STR, W4, 88, b4, nullptr, out, 88, N, 0);
}

// round 6
// speedup vs baseline: 1.6089x; 1.3884x over previous
#include <cuda_runtime.h>
#include <cuda_fp16.h>
#include <cstdint>
#include <math.h>

#define MAXN 100000
#define MAXE 1600000

// ---------------- scratch (device globals; no allocation allowed) ----------
__device__ __align__(16) __half g_t1[MAXN * 72];  // GEMM1 out (d=65)
__device__ __align__(16) __half g_h1[MAXN * 80];  // agg1 out  (d=65, Kp=80)
__device__ __align__(16) __half g_t2[MAXN * 56];  // GEMM2 out (d=50)
__device__ __align__(16) __half g_h2[MAXN * 56];  // agg2 out  (d=50)
__device__ __align__(16) __half g_a3[MAXN * 64];  // agg3 out  (d=50, Kp=64)
__device__ __align__(16) __half g_t3[MAXN * 72];  // GEMM3 out (d=65)
__device__ __align__(16) __half g_a4[MAXN * 80];  // agg4 out  (d=65, Kp=80)
__device__ __align__(16) __half g_wh[23040];      // packed fp16 weights
__device__ float g_dinv[MAXN];
__device__ int   g_cnt[MAXN];
__device__ int   g_fill[MAXN];
__device__ int   g_rowptr[MAXN + 1];
__device__ int   g_csr[MAXE];
__device__ int   g_bsum[128];

// weight segment offsets in g_wh (halfs)
#define WOFF1 0
#define WOFF2 6912
#define WOFF3 11392
#define WOFF4 16000

// ---------------- CSR build ------------------------------------------------
__global__ void k_count(const int* __restrict__ dst, int E, int* __restrict__ cnt) {
    int e = blockIdx.x * blockDim.x + threadIdx.x;
    if (e < E) atomicAdd(&cnt[dst[e]], 1);
}

__global__ void k_dinv(const int* __restrict__ cnt, float* __restrict__ dinv, int n) {
    int i = blockIdx.x * blockDim.x + threadIdx.x;
    if (i < n) dinv[i] = rsqrtf((float)(cnt[i] + 1));
}

__global__ void k_scan_block(const int* __restrict__ cnt, int n,
                             int* __restrict__ incl, int* __restrict__ bsum) {
    __shared__ int sh[1024];
    int tid = threadIdx.x;
    int gid = blockIdx.x * 1024 + tid;
    int v = (gid < n) ? cnt[gid] : 0;
    sh[tid] = v;
    __syncthreads();
    for (int off = 1; off < 1024; off <<= 1) {
        int t = 0;
        if (tid >= off) t = sh[tid - off];
        __syncthreads();
        sh[tid] += t;
        __syncthreads();
    }
    if (gid < n) incl[gid] = sh[tid];
    if (tid == 1023) bsum[blockIdx.x] = sh[1023];
}

__global__ void k_scan_sums(int* bsum, int nb) {
    __shared__ int sh[128];
    int tid = threadIdx.x;
    int v = (tid < nb) ? bsum[tid] : 0;
    sh[tid] = v;
    __syncthreads();
    for (int off = 1; off < 128; off <<= 1) {
        int t = 0;
        if (tid >= off) t = sh[tid - off];
        __syncthreads();
        sh[tid] += t;
        __syncthreads();
    }
    if (tid < nb) bsum[tid] = (tid == 0) ? 0 : sh[tid - 1];
}

__global__ void k_finalize(const int* __restrict__ bsum, int* __restrict__ rowptr,
                           int* __restrict__ fill, int n) {
    int i = blockIdx.x * blockDim.x + threadIdx.x;
    if (i < n) {
        rowptr[i + 1] += bsum[i >> 10];
        fill[i] = 0;
        if (i == 0) rowptr[0] = 0;
    }
}

__global__ void k_fill(const int* __restrict__ src, const int* __restrict__ dst, int E,
                       const int* __restrict__ rowptr, int* __restrict__ fill,
                       int* __restrict__ csr) {
    int e = blockIdx.x * blockDim.x + threadIdx.x;
    if (e < E) {
        int d = dst[e];
        int p = atomicAdd(&fill[d], 1);
        csr[rowptr[d] + p] = src[e];
    }
}

// ---------------- weight conversion (fp32 -> fp16, zero-padded) ------------
__global__ void k_prep_w(const float* __restrict__ W1, const float* __restrict__ W2,
                         const float* __restrict__ W3, const float* __restrict__ W4,
                         __half* __restrict__ o) {
    int i = blockIdx.x * blockDim.x + threadIdx.x;
    if (i < 6912) {                                    // W1 [88x65] -> [96x72]
        int kk = i / 72;
        int nn = i - kk * 72;
        o[WOFF1 + i] = __float2half((kk < 88 && nn < 65) ? W1[kk * 65 + nn] : 0.f);
    } else if (i < 11392) {                            // W2 [65x50] -> [80x56]
        int j = i - 6912;
        int kk = j / 56;
        int nn = j - kk * 56;
        o[WOFF2 + j] = __float2half((kk < 65 && nn < 50) ? W2[kk * 50 + nn] : 0.f);
    } else if (i < 16000) {                            // W3 [50x65] -> [64x72]
        int j = i - 11392;
        int kk = j / 72;
        int nn = j - kk * 72;
        o[WOFF3 + j] = __float2half((kk < 50 && nn < 65) ? W3[kk * 65 + nn] : 0.f);
    } else if (i < 23040) {                            // W4 [65x88] -> [80x88]
        int j = i - 16000;
        int kk = j / 88;
        int nn = j - kk * 88;
        o[WOFF4 + j] = __float2half((kk < 65 && nn < 88) ? W4[kk * 88 + nn] : 0.f);
    }
}

// ---------------- tensor-core GEMM helpers ---------------------------------
__device__ __forceinline__ void ldsm_x4(unsigned int& a0, unsigned int& a1,
                                        unsigned int& a2, unsigned int& a3,
                                        const __half* p) {
    unsigned int addr = (unsigned int)__cvta_generic_to_shared((const void*)p);
    asm volatile("ldmatrix.sync.aligned.m8n8.x4.shared.b16 {%0,%1,%2,%3}, [%4];"
                 : "=r"(a0), "=r"(a1), "=r"(a2), "=r"(a3)
                 : "r"(addr));
}

__device__ __forceinline__ void ldsm_x2t(unsigned int& b0, unsigned int& b1,
                                         const __half* p) {
    unsigned int addr = (unsigned int)__cvta_generic_to_shared((const void*)p);
    asm volatile("ldmatrix.sync.aligned.m8n8.x2.trans.shared.b16 {%0,%1}, [%2];"
                 : "=r"(b0), "=r"(b1)
                 : "r"(addr));
}

__device__ __forceinline__ void mma16816(float& d0, float& d1, float& d2, float& d3,
                                         unsigned int a0, unsigned int a1,
                                         unsigned int a2, unsigned int a3,
                                         unsigned int b0, unsigned int b1) {
    asm volatile("mma.sync.aligned.m16n8k16.row.col.f32.f16.f16.f32 "
                 "{%0,%1,%2,%3}, {%4,%5,%6,%7}, {%8,%9}, {%0,%1,%2,%3};"
                 : "+f"(d0), "+f"(d1), "+f"(d2), "+f"(d3)
                 : "r"(a0), "r"(a1), "r"(a2), "r"(a3), "r"(b0), "r"(b1));
}

// C[N, Np] = A[N, Kp] * B[Kp, Np]; block = 128 rows, 256 threads (8 warps).
// AF32=1: A is fp32, lda=88 elements (layer-1 input x), converted in smem stage.
// Epilogue: (+bias[col<M]) (RELU) (xdinv[row] if SCALE); cols in [M,Np) -> 0.
template <int Kp, int Np, int AF32, int RELU, int SCALE, int OUT_HALF>
__global__ void k_gemm_tc(const void* Av,
                          const __half* __restrict__ B,
                          const float* __restrict__ bias,
                          const float* __restrict__ dinv,
                          void* Cv, int ldc, int M, int N) {
    const int KT = Kp / 16;
    const int NT = Np / 8;
    const int LDA = Kp + 8;
    const int LDB = Np + 8;
    __shared__ __align__(16) __half sA[128 * (Kp + 8)];
    __shared__ __align__(16) __half sB[Kp * (Np + 8)];

    int tid = threadIdx.x;
    int warp = tid >> 5;
    int lane = tid & 31;
    int r0 = blockIdx.x * 128;

    // --- stage A into shared (fp16) ---
    if (AF32) {
        const float4* Ag = (const float4*)Av;            // 88 floats = 22 float4/row
        for (int i = tid; i < 128 * 22; i += 256) {
            int r = i / 22;
            int v = i - r * 22;
            int gr = r0 + r;
            float4 f = make_float4(0.f, 0.f, 0.f, 0.f);
            if (gr < N) f = Ag[(size_t)gr * 22 + v];
            __half2* p = (__half2*)&sA[r * LDA + v * 4];
            p[0] = __floats2half2_rn(f.x, f.y);
            p[1] = __floats2half2_rn(f.z, f.w);
        }
        for (int i = tid; i < 128 * 4; i += 256) {       // zero cols 88..95
            int r = i >> 2;
            int v = i & 3;
            __half2* p = (__half2*)&sA[r * LDA + 88 + 2 * v];
            p[0] = __floats2half2_rn(0.f, 0.f);
        }
    } else {
        const int HV = Kp / 8;                           // uint4 per row
        const uint4* Ag = (const uint4*)Av;
        for (int i = tid; i < 128 * HV; i += 256) {
            int r = i / HV;
            int v = i - r * HV;
            int gr = r0 + r;
            uint4 q = make_uint4(0u, 0u, 0u, 0u);
            if (gr < N) q = Ag[(size_t)gr * HV + v];
            *(uint4*)&sA[r * LDA + v * 8] = q;
        }
    }
    // --- stage B ---
    {
        const int BV = Np / 8;
        const uint4* Bg = (const uint4*)B;
        for (int i = tid; i < Kp * BV; i += 256) {
            int kk = i / BV;
            int v = i - kk * BV;
            *(uint4*)&sB[kk * LDB + v * 8] = Bg[kk * BV + v];
        }
    }
    __syncthreads();

    float acc[NT][4];
#pragma unroll
    for (int nt = 0; nt < NT; nt++) {
#pragma unroll
        for (int q = 0; q < 4; q++) acc[nt][q] = 0.f;
    }

#pragma unroll
    for (int kt = 0; kt < KT; kt++) {
        unsigned int a0, a1, a2, a3;
        const __half* pa = &sA[(warp * 16 + (lane & 15)) * LDA + kt * 16 + (lane >> 4) * 8];
        ldsm_x4(a0, a1, a2, a3, pa);
#pragma unroll
        for (int nt = 0; nt < NT; nt++) {
            unsigned int b0, b1;
            const __half* pb = &sB[(kt * 16 + (lane & 15)) * LDB + nt * 8];
            ldsm_x2t(b0, b1, pb);
            mma16816(acc[nt][0], acc[nt][1], acc[nt][2], acc[nt][3],
                     a0, a1, a2, a3, b0, b1);
        }
    }

    // --- epilogue ---
    int row = r0 + warp * 16 + (lane >> 2);
    int colb = (lane & 3) * 2;
    float sc0 = 1.f;
    float sc1 = 1.f;
    if (SCALE) {
        sc0 = (row < N) ? dinv[row] : 0.f;
        sc1 = (row + 8 < N) ? dinv[row + 8] : 0.f;
    }
#pragma unroll
    for (int nt = 0; nt < NT; nt++) {
        int c0 = nt * 8 + colb;
        float b0v = 0.f;
        float b1v = 0.f;
        if (bias != nullptr) {
            b0v = (c0 < M) ? bias[c0] : 0.f;
            b1v = (c0 + 1 < M) ? bias[c0 + 1] : 0.f;
        }
        float v00 = acc[nt][0] + b0v;
        float v01 = acc[nt][1] + b1v;
        float v10 = acc[nt][2] + b0v;
        float v11 = acc[nt][3] + b1v;
        if (RELU) {
            v00 = fmaxf(v00, 0.f); v01 = fmaxf(v01, 0.f);
            v10 = fmaxf(v10, 0.f); v11 = fmaxf(v11, 0.f);
        }
        v00 *= sc0; v01 *= sc0; v10 *= sc1; v11 *= sc1;
        if (c0 >= M)     { v00 = 0.f; v10 = 0.f; }
        if (c0 + 1 >= M) { v01 = 0.f; v11 = 0.f; }
        if (OUT_HALF) {
            __half* C = (__half*)Cv;
            if (row < N)
                *(__half2*)&C[(size_t)row * ldc + c0] = __floats2half2_rn(v00, v01);
            if (row + 8 < N)
                *(__half2*)&C[(size_t)(row + 8) * ldc + c0] = __floats2half2_rn(v10, v11);
        } else {
            float* C = (float*)Cv;
            if (row < N)
                *(float2*)&C[(size_t)row * ldc + c0] = make_float2(v00, v01);
            if (row + 8 < N)
                *(float2*)&C[(size_t)(row + 8) * ldc + c0] = make_float2(v10, v11);
        }
    }
}

// ---------------- aggregation (fp16 gather, fp32 accumulate) ---------------
// o[i] = epi( dinv_i * (sum_{s in N(i)} t[s] + t[i]) ); rows pre-scaled by dinv_src.
// D2 = real half2 per row; SIN2/SOUT2 = strides in half2. Output pads -> 0.
template <int D2, int SIN2, int SOUT2>
__global__ void k_agg(const __half2* __restrict__ t, __half2* __restrict__ o,
                      const int* __restrict__ rowptr, const int* __restrict__ csr,
                      const float* __restrict__ dinv,
                      const float* __restrict__ bias, int d,
                      int relu, int post2, int N) {
    const int NCH = (D2 + 31) / 32;
    const int NCHO = (SOUT2 + 31) / 32;
    int node = (blockIdx.x * blockDim.x + threadIdx.x) >> 5;
    int lane = threadIdx.x & 31;
    if (node >= N) return;
    int beg = rowptr[node];
    int end = rowptr[node + 1];

    float2 acc[NCH];
#pragma unroll
    for (int c = 0; c < NCH; c++) acc[c] = make_float2(0.f, 0.f);

    int j = beg;
    for (; j + 4 <= end; j += 4) {
        int s0 = __ldg(&csr[j]);
        int s1 = __ldg(&csr[j + 1]);
        int s2 = __ldg(&csr[j + 2]);
        int s3 = __ldg(&csr[j + 3]);
        const __half2* r0 = t + (size_t)s0 * SIN2;
        const __half2* r1 = t + (size_t)s1 * SIN2;
        const __half2* r2 = t + (size_t)s2 * SIN2;
        const __half2* r3 = t + (size_t)s3 * SIN2;
#pragma unroll
        for (int c = 0; c < NCH; c++) {
            int idx = c * 32 + lane;
            if (idx < D2) {
                float2 f0 = __half22float2(__ldg(&r0[idx]));
                float2 f1 = __half22float2(__ldg(&r1[idx]));
                float2 f2 = __half22float2(__ldg(&r2[idx]));
                float2 f3 = __half22float2(__ldg(&r3[idx]));
                acc[c].x += (f0.x + f1.x) + (f2.x + f3.x);
                acc[c].y += (f0.y + f1.y) + (f2.y + f3.y);
            }
        }
    }
    for (; j < end; j++) {
        int s0 = __ldg(&csr[j]);
        const __half2* r0 = t + (size_t)s0 * SIN2;
#pragma unroll
        for (int c = 0; c < NCH; c++) {
            int idx = c * 32 + lane;
            if (idx < D2) {
                float2 f0 = __half22float2(__ldg(&r0[idx]));
                acc[c].x += f0.x;
                acc[c].y += f0.y;
            }
        }
    }
    // self loop (row already carries dinv_i)
    {
        const __half2* ri = t + (size_t)node * SIN2;
#pragma unroll
        for (int c = 0; c < NCH; c++) {
            int idx = c * 32 + lane;
            if (idx < D2) {
                float2 f = __half22float2(__ldg(&ri[idx]));
                acc[c].x += f.x;
                acc[c].y += f.y;
            }
        }
    }

    float di = dinv[node];
#pragma unroll
    for (int c = 0; c < NCHO; c++) {
        int idx = c * 32 + lane;
        if (idx < D2) {
            int col0 = 2 * idx;
            int col1 = 2 * idx + 1;
            float vx = acc[c].x * di;
            float vy = acc[c].y * di;
            if (bias != nullptr) {
                vx += (col0 < d) ? bias[col0] : 0.f;
                vy += (col1 < d) ? bias[col1] : 0.f;
            }
            if (relu) { vx = fmaxf(vx, 0.f); vy = fmaxf(vy, 0.f); }
            if (post2) { vx *= di; vy *= di; }
            if (col0 >= d) vx = 0.f;
            if (col1 >= d) vy = 0.f;
            o[(size_t)node * SOUT2 + idx] = __floats2half2_rn(vx, vy);
        } else if (idx < SOUT2) {
            o[(size_t)node * SOUT2 + idx] = __floats2half2_rn(0.f, 0.f);
        }
    }
}

// ---------------- launch ----------------------------------------------------
extern "C" void kernel_launch(void* const* d_in, const int* in_sizes, int n_in,
                              void* d_out, int out_size) {
    const float* x  = (const float*)d_in[0];
    const float* W1 = (const float*)d_in[1];
    const float* b1 = (const float*)d_in[2];
    const float* W2 = (const float*)d_in[3];
    const float* b2 = (const float*)d_in[4];
    const float* W3 = (const float*)d_in[5];
    const float* b3 = (const float*)d_in[6];
    const float* W4 = (const float*)d_in[7];
    const float* b4 = (const float*)d_in[8];
    const int*   ei = (const int*)d_in[9];

    int N = in_sizes[0] / 88;
    int E = in_sizes[9] / 2;
    const int* src = ei;
    const int* dst = ei + E;
    float* out = (float*)d_out;

    __half *t1, *h1, *t2, *h2, *a3, *t3, *a4, *wh;
    float* dinv;
    int *cnt, *fill, *rowptr, *csr, *bsum;
    cudaGetSymbolAddress((void**)&t1, g_t1);
    cudaGetSymbolAddress((void**)&h1, g_h1);
    cudaGetSymbolAddress((void**)&t2, g_t2);
    cudaGetSymbolAddress((void**)&h2, g_h2);
    cudaGetSymbolAddress((void**)&a3, g_a3);
    cudaGetSymbolAddress((void**)&t3, g_t3);
    cudaGetSymbolAddress((void**)&a4, g_a4);
    cudaGetSymbolAddress((void**)&wh, g_wh);
    cudaGetSymbolAddress((void**)&dinv, g_dinv);
    cudaGetSymbolAddress((void**)&cnt, g_cnt);
    cudaGetSymbolAddress((void**)&fill, g_fill);
    cudaGetSymbolAddress((void**)&rowptr, g_rowptr);
    cudaGetSymbolAddress((void**)&csr, g_csr);
    cudaGetSymbolAddress((void**)&bsum, g_bsum);

    int aggBlocks = (N * 32 + 255) / 256;
    int gemmBlocks = (N + 127) / 128;
    int nb = (N + 1023) / 1024;

    cudaMemsetAsync(cnt, 0, (size_t)N * sizeof(int));
    k_count<<<(E + 255) / 256, 256>>>(dst, E, cnt);
    k_dinv<<<(N + 255) / 256, 256>>>(cnt, dinv, N);
    k_prep_w<<<90, 256>>>(W1, W2, W3, W4, wh);

    // profiled slot #4: L1 tensor GEMM  t1 = dinv o (x@W1)
    k_gemm_tc<96, 72, 1, 0, 1, 1><<<gemmBlocks, 256>>>(
        (const void*)x, wh + WOFF1, nullptr, dinv, (void*)t1, 72, 65, N);

    // CSR build
    k_scan_block<<<nb, 1024>>>(cnt, N, rowptr + 1, bsum);
    k_scan_sums<<<1, 128>>>(bsum, nb);
    k_finalize<<<(N + 255) / 256, 256>>>(bsum, rowptr, fill, N);
    k_fill<<<(E + 255) / 256, 256>>>(src, dst, E, rowptr, fill, csr);

    // L1 agg: h1 = relu(di*S(t1) + b1)
    k_agg<33, 36, 40><<<aggBlocks, 256>>>((const __half2*)t1, (__half2*)h1,
                                          rowptr, csr, dinv, b1, 65, 1, 0, N);
    // L2: t2 = dinv o (h1@W2); h2 = dinv o (di*S(t2) + b2)
    k_gemm_tc<80, 56, 0, 0, 1, 1><<<gemmBlocks, 256>>>(
        (const void*)h1, wh + WOFF2, nullptr, dinv, (void*)t2, 56, 50, N);
    k_agg<25, 28, 28><<<aggBlocks, 256>>>((const __half2*)t2, (__half2*)h2,
                                          rowptr, csr, dinv, b2, 50, 0, 1, N);
    // L3: a3 = di*S(h2); t3 = dinv o relu(a3@W3 + b3)
    k_agg<25, 28, 32><<<aggBlocks, 256>>>((const __half2*)h2, (__half2*)a3,
                                          rowptr, csr, dinv, nullptr, 50, 0, 0, N);
    k_gemm_tc<64, 72, 0, 1, 1, 1><<<gemmBlocks, 256>>>(
        (const void*)a3, wh + WOFF3, b3, dinv, (void*)t3, 72, 65, N);
    // L4: a4 = di*S(t3); out = a4@W4 + b4
    k_agg<33, 36, 40><<<aggBlocks, 256>>>((const __half2*)t3, (__half2*)a4,
                                          rowptr, csr, dinv, nullptr, 65, 0, 0, N);
    k_gemm_tc<80, 88, 0, 0, 0, 0><<<gemmBlocks, 256>>>(
        (const void*)a4, wh + WOFF4, b4, nullptr, (void*)out, 88, 88, N);
}

// round 7
// speedup vs baseline: 1.6543x; 1.0282x over previous
#include <cuda_runtime.h>
#include <cuda_fp16.h>
#include <cstdint>
#include <math.h>

#define MAXN 100000
#define MAXE 1600000

// ---------------- scratch (device globals; no allocation allowed) ----------
__device__ __align__(16) __half g_t1[MAXN * 72];  // GEMM1 out (d=65)
__device__ __align__(16) __half g_h1[MAXN * 80];  // agg1 out  (d=65, Kp=80)
__device__ __align__(16) __half g_t2[MAXN * 56];  // GEMM2 out (d=50)
__device__ __align__(16) __half g_h2[MAXN * 56];  // agg2 out  (d=50)
__device__ __align__(16) __half g_a3[MAXN * 64];  // agg3 out  (d=50, Kp=64)
__device__ __align__(16) __half g_t3[MAXN * 72];  // GEMM3 out (d=65)
__device__ __align__(16) __half g_a4[MAXN * 80];  // agg4 out  (d=65, Kp=80)
__device__ __align__(16) __half g_wh[23040];      // packed fp16 weights
__device__ float g_dinv[MAXN];
__device__ int   g_cnt[MAXN];
__device__ int   g_fill[MAXN];
__device__ int   g_rowptr[MAXN + 1];
__device__ int   g_csr[MAXE];
__device__ int   g_bsum[128];

#define WOFF1 0
#define WOFF2 6912
#define WOFF3 11392
#define WOFF4 16000

// ---------------- CSR build ------------------------------------------------
__global__ void k_count(const int* __restrict__ dst, int E, int* __restrict__ cnt) {
    int e = blockIdx.x * blockDim.x + threadIdx.x;
    if (e < E) atomicAdd(&cnt[dst[e]], 1);
}

__global__ void k_dinv(const int* __restrict__ cnt, float* __restrict__ dinv, int n) {
    int i = blockIdx.x * blockDim.x + threadIdx.x;
    if (i < n) dinv[i] = rsqrtf((float)(cnt[i] + 1));
}

__global__ void k_scan_block(const int* __restrict__ cnt, int n,
                             int* __restrict__ incl, int* __restrict__ bsum) {
    __shared__ int sh[1024];
    int tid = threadIdx.x;
    int gid = blockIdx.x * 1024 + tid;
    int v = (gid < n) ? cnt[gid] : 0;
    sh[tid] = v;
    __syncthreads();
    for (int off = 1; off < 1024; off <<= 1) {
        int t = 0;
        if (tid >= off) t = sh[tid - off];
        __syncthreads();
        sh[tid] += t;
        __syncthreads();
    }
    if (gid < n) incl[gid] = sh[tid];
    if (tid == 1023) bsum[blockIdx.x] = sh[1023];
}

__global__ void k_scan_sums(int* bsum, int nb) {
    __shared__ int sh[128];
    int tid = threadIdx.x;
    int v = (tid < nb) ? bsum[tid] : 0;
    sh[tid] = v;
    __syncthreads();
    for (int off = 1; off < 128; off <<= 1) {
        int t = 0;
        if (tid >= off) t = sh[tid - off];
        __syncthreads();
        sh[tid] += t;
        __syncthreads();
    }
    if (tid < nb) bsum[tid] = (tid == 0) ? 0 : sh[tid - 1];
}

__global__ void k_finalize(const int* __restrict__ bsum, int* __restrict__ rowptr,
                           int* __restrict__ fill, int n) {
    int i = blockIdx.x * blockDim.x + threadIdx.x;
    if (i < n) {
        rowptr[i + 1] += bsum[i >> 10];
        fill[i] = 0;
        if (i == 0) rowptr[0] = 0;
    }
}

__global__ void k_fill(const int* __restrict__ src, const int* __restrict__ dst, int E,
                       const int* __restrict__ rowptr, int* __restrict__ fill,
                       int* __restrict__ csr) {
    int e = blockIdx.x * blockDim.x + threadIdx.x;
    if (e < E) {
        int d = dst[e];
        int p = atomicAdd(&fill[d], 1);
        csr[rowptr[d] + p] = src[e];
    }
}

// ---------------- weight conversion (fp32 -> fp16, zero-padded) ------------
__global__ void k_prep_w(const float* __restrict__ W1, const float* __restrict__ W2,
                         const float* __restrict__ W3, const float* __restrict__ W4,
                         __half* __restrict__ o) {
    int i = blockIdx.x * blockDim.x + threadIdx.x;
    if (i < 6912) {                                    // W1 [88x65] -> [96x72]
        int kk = i / 72;
        int nn = i - kk * 72;
        o[WOFF1 + i] = __float2half((kk < 88 && nn < 65) ? W1[kk * 65 + nn] : 0.f);
    } else if (i < 11392) {                            // W2 [65x50] -> [80x56]
        int j = i - 6912;
        int kk = j / 56;
        int nn = j - kk * 56;
        o[WOFF2 + j] = __float2half((kk < 65 && nn < 50) ? W2[kk * 50 + nn] : 0.f);
    } else if (i < 16000) {                            // W3 [50x65] -> [64x72]
        int j = i - 11392;
        int kk = j / 72;
        int nn = j - kk * 72;
        o[WOFF3 + j] = __float2half((kk < 50 && nn < 65) ? W3[kk * 65 + nn] : 0.f);
    } else if (i < 23040) {                            // W4 [65x88] -> [80x88]
        int j = i - 16000;
        int kk = j / 88;
        int nn = j - kk * 88;
        o[WOFF4 + j] = __float2half((kk < 65 && nn < 88) ? W4[kk * 88 + nn] : 0.f);
    }
}

// ---------------- tensor-core GEMM helpers ---------------------------------
__device__ __forceinline__ void ldsm_x4(unsigned int& a0, unsigned int& a1,
                                        unsigned int& a2, unsigned int& a3,
                                        const __half* p) {
    unsigned int addr = (unsigned int)__cvta_generic_to_shared((const void*)p);
    asm volatile("ldmatrix.sync.aligned.m8n8.x4.shared.b16 {%0,%1,%2,%3}, [%4];"
                 : "=r"(a0), "=r"(a1), "=r"(a2), "=r"(a3)
                 : "r"(addr));
}

__device__ __forceinline__ void ldsm_x2t(unsigned int& b0, unsigned int& b1,
                                         const __half* p) {
    unsigned int addr = (unsigned int)__cvta_generic_to_shared((const void*)p);
    asm volatile("ldmatrix.sync.aligned.m8n8.x2.trans.shared.b16 {%0,%1}, [%2];"
                 : "=r"(b0), "=r"(b1)
                 : "r"(addr));
}

__device__ __forceinline__ void mma16816(float& d0, float& d1, float& d2, float& d3,
                                         unsigned int a0, unsigned int a1,
                                         unsigned int a2, unsigned int a3,
                                         unsigned int b0, unsigned int b1) {
    asm volatile("mma.sync.aligned.m16n8k16.row.col.f32.f16.f16.f32 "
                 "{%0,%1,%2,%3}, {%4,%5,%6,%7}, {%8,%9}, {%0,%1,%2,%3};"
                 : "+f"(d0), "+f"(d1), "+f"(d2), "+f"(d3)
                 : "r"(a0), "r"(a1), "r"(a2), "r"(a3), "r"(b0), "r"(b1));
}

// C[N, Np] = A[N, Kp] * B[Kp, Np]; block = 256 rows, 256 threads (8 warps).
// Warp owns 32 rows (two 16-row MMA tiles) -> each B fragment feeds 2 MMAs.
// LDA = Kp+8 (=8 mod 16: conflict-free ldmatrix), LDB = Np (already =8 mod 16).
// Dynamic smem. Epilogue: (+bias[col<M])(RELU)(xdinv if SCALE); cols>=M -> 0.
template <int Kp, int Np, int AF32, int RELU, int SCALE, int OUT_HALF>
__global__ void __launch_bounds__(256)
k_gemm_tc(const void* Av,
          const __half* __restrict__ B,
          const float* __restrict__ bias,
          const float* __restrict__ dinv,
          void* Cv, int ldc, int M, int N) {
    const int KT = Kp / 16;
    const int NT = Np / 8;
    const int LDA = Kp + 8;
    const int LDB = Np;
    extern __shared__ char smem_raw[];
    __half* sA = (__half*)smem_raw;                 // 256 x LDA
    __half* sB = (__half*)smem_raw + 256 * LDA;     // Kp x LDB

    int tid = threadIdx.x;
    int warp = tid >> 5;
    int lane = tid & 31;
    int r0 = blockIdx.x * 256;

    // --- stage A (fp16 into sA) ---
    if (AF32) {
        const float4* Ag = (const float4*)Av;       // 88 floats = 22 float4/row
        for (int i = tid; i < 256 * 22; i += 256) {
            int r = i / 22;
            int v = i - r * 22;
            int gr = r0 + r;
            float4 f = make_float4(0.f, 0.f, 0.f, 0.f);
            if (gr < N) f = Ag[(size_t)gr * 22 + v];
            __half2* p = (__half2*)&sA[r * LDA + v * 4];
            p[0] = __floats2half2_rn(f.x, f.y);
            p[1] = __floats2half2_rn(f.z, f.w);
        }
        for (int i = tid; i < 256 * 4; i += 256) {   // zero cols 88..95
            int r = i >> 2;
            int v = i & 3;
            *(__half2*)&sA[r * LDA + 88 + 2 * v] = __floats2half2_rn(0.f, 0.f);
        }
    } else {
        const int HV = Kp / 8;
        const uint4* Ag = (const uint4*)Av;
        for (int i = tid; i < 256 * HV; i += 256) {
            int r = i / HV;
            int v = i - r * HV;
            int gr = r0 + r;
            uint4 q = make_uint4(0u, 0u, 0u, 0u);
            if (gr < N) q = Ag[(size_t)gr * HV + v];
            *(uint4*)&sA[r * LDA + v * 8] = q;
        }
    }
    // --- stage B ---
    {
        const int BV = Np / 8;
        const uint4* Bg = (const uint4*)B;
        for (int i = tid; i < Kp * BV; i += 256) {
            int kk = i / BV;
            int v = i - kk * BV;
            *(uint4*)&sB[kk * LDB + v * 8] = Bg[i];
        }
    }
    __syncthreads();

    float acc0[NT][4];
    float acc1[NT][4];
#pragma unroll
    for (int nt = 0; nt < NT; nt++) {
#pragma unroll
        for (int q = 0; q < 4; q++) { acc0[nt][q] = 0.f; acc1[nt][q] = 0.f; }
    }

#pragma unroll
    for (int kt = 0; kt < KT; kt++) {
        unsigned int a0, a1, a2, a3, c0r, c1r, c2r, c3r;
        const __half* pa0 = &sA[(warp * 32 + (lane & 15)) * LDA + kt * 16 + (lane >> 4) * 8];
        const __half* pa1 = pa0 + 16 * LDA;
        ldsm_x4(a0, a1, a2, a3, pa0);
        ldsm_x4(c0r, c1r, c2r, c3r, pa1);
#pragma unroll
        for (int nt = 0; nt < NT; nt++) {
            unsigned int b0, b1;
            const __half* pb = &sB[(kt * 16 + (lane & 15)) * LDB + nt * 8];
            ldsm_x2t(b0, b1, pb);
            mma16816(acc0[nt][0], acc0[nt][1], acc0[nt][2], acc0[nt][3],
                     a0, a1, a2, a3, b0, b1);
            mma16816(acc1[nt][0], acc1[nt][1], acc1[nt][2], acc1[nt][3],
                     c0r, c1r, c2r, c3r, b0, b1);
        }
    }

    // --- epilogue: warp rows = r0 + warp*32 + {g, g+8, g+16, g+24}, g=lane>>2
    int rowA = r0 + warp * 32 + (lane >> 2);
    int colb = (lane & 3) * 2;
    float sc[4] = {1.f, 1.f, 1.f, 1.f};
    if (SCALE) {
#pragma unroll
        for (int t = 0; t < 4; t++) {
            int rr = rowA + t * 8;
            sc[t] = (rr < N) ? dinv[rr] : 0.f;
        }
    }
#pragma unroll
    for (int nt = 0; nt < NT; nt++) {
        int c0 = nt * 8 + colb;
        float b0v = 0.f;
        float b1v = 0.f;
        if (bias != nullptr) {
            b0v = (c0 < M) ? bias[c0] : 0.f;
            b1v = (c0 + 1 < M) ? bias[c0 + 1] : 0.f;
        }
        float vx[4], vy[4];
        vx[0] = acc0[nt][0]; vy[0] = acc0[nt][1];
        vx[1] = acc0[nt][2]; vy[1] = acc0[nt][3];
        vx[2] = acc1[nt][0]; vy[2] = acc1[nt][1];
        vx[3] = acc1[nt][2]; vy[3] = acc1[nt][3];
#pragma unroll
        for (int t = 0; t < 4; t++) {
            int rr = rowA + t * 8;
            if (rr >= N) continue;
            float v0 = vx[t] + b0v;
            float v1 = vy[t] + b1v;
            if (RELU) { v0 = fmaxf(v0, 0.f); v1 = fmaxf(v1, 0.f); }
            v0 *= sc[t]; v1 *= sc[t];
            if (c0 >= M)     v0 = 0.f;
            if (c0 + 1 >= M) v1 = 0.f;
            if (OUT_HALF) {
                __half* C = (__half*)Cv;
                *(__half2*)&C[(size_t)rr * ldc + c0] = __floats2half2_rn(v0, v1);
            } else {
                float* C = (float*)Cv;
                *(float2*)&C[(size_t)rr * ldc + c0] = make_float2(v0, v1);
            }
        }
    }
}

// ---------------- aggregation (uint2 fp16 gather, fp32 accumulate) ---------
// o[i] = epi( dinv_i * (sum_{s in N(i)} t[s] + t[i]) ); rows pre-scaled by dinv_src.
// Units of 4 halfs (uint2). D4 = active lanes; SIN4/SOUT4 = strides in uint2.
template <int D4, int SIN4, int SOUT4>
__global__ void k_agg(const uint2* __restrict__ t, uint2* __restrict__ o,
                      const int* __restrict__ rowptr, const int* __restrict__ csr,
                      const float* __restrict__ dinv,
                      const float* __restrict__ bias, int d,
                      int relu, int post2, int N) {
    int node = (blockIdx.x * blockDim.x + threadIdx.x) >> 5;
    int lane = threadIdx.x & 31;
    if (node >= N) return;
    int beg = rowptr[node];
    int end = rowptr[node + 1];
    bool act = (lane < D4);

    float a0 = 0.f, a1 = 0.f, a2 = 0.f, a3 = 0.f;

    int j = beg;
    for (; j + 4 <= end; j += 4) {
        int s0 = __ldg(&csr[j]);
        int s1 = __ldg(&csr[j + 1]);
        int s2 = __ldg(&csr[j + 2]);
        int s3 = __ldg(&csr[j + 3]);
        if (act) {
            uint2 q0 = __ldg(&t[(size_t)s0 * SIN4 + lane]);
            uint2 q1 = __ldg(&t[(size_t)s1 * SIN4 + lane]);
            uint2 q2 = __ldg(&t[(size_t)s2 * SIN4 + lane]);
            uint2 q3 = __ldg(&t[(size_t)s3 * SIN4 + lane]);
            float2 f;
            f = __half22float2(*(__half2*)&q0.x); a0 += f.x; a1 += f.y;
            f = __half22float2(*(__half2*)&q0.y); a2 += f.x; a3 += f.y;
            f = __half22float2(*(__half2*)&q1.x); a0 += f.x; a1 += f.y;
            f = __half22float2(*(__half2*)&q1.y); a2 += f.x; a3 += f.y;
            f = __half22float2(*(__half2*)&q2.x); a0 += f.x; a1 += f.y;
            f = __half22float2(*(__half2*)&q2.y); a2 += f.x; a3 += f.y;
            f = __half22float2(*(__half2*)&q3.x); a0 += f.x; a1 += f.y;
            f = __half22float2(*(__half2*)&q3.y); a2 += f.x; a3 += f.y;
        }
    }
    for (; j < end; j++) {
        int s0 = __ldg(&csr[j]);
        if (act) {
            uint2 q0 = __ldg(&t[(size_t)s0 * SIN4 + lane]);
            float2 f;
            f = __half22float2(*(__half2*)&q0.x); a0 += f.x; a1 += f.y;
            f = __half22float2(*(__half2*)&q0.y); a2 += f.x; a3 += f.y;
        }
    }
    // self loop (row already carries dinv_i)
    if (act) {
        uint2 q = __ldg(&t[(size_t)node * SIN4 + lane]);
        float2 f;
        f = __half22float2(*(__half2*)&q.x); a0 += f.x; a1 += f.y;
        f = __half22float2(*(__half2*)&q.y); a2 += f.x; a3 += f.y;
    }

    float di = dinv[node];
    if (act) {
        int c0 = 4 * lane;
        float v0 = a0 * di, v1 = a1 * di, v2 = a2 * di, v3 = a3 * di;
        if (bias != nullptr) {
            v0 += (c0 < d) ? bias[c0] : 0.f;
            v1 += (c0 + 1 < d) ? bias[c0 + 1] : 0.f;
            v2 += (c0 + 2 < d) ? bias[c0 + 2] : 0.f;
            v3 += (c0 + 3 < d) ? bias[c0 + 3] : 0.f;
        }
        if (relu) {
            v0 = fmaxf(v0, 0.f); v1 = fmaxf(v1, 0.f);
            v2 = fmaxf(v2, 0.f); v3 = fmaxf(v3, 0.f);
        }
        if (post2) { v0 *= di; v1 *= di; v2 *= di; v3 *= di; }
        if (c0 >= d)     v0 = 0.f;
        if (c0 + 1 >= d) v1 = 0.f;
        if (c0 + 2 >= d) v2 = 0.f;
        if (c0 + 3 >= d) v3 = 0.f;
        uint2 w;
        *(__half2*)&w.x = __floats2half2_rn(v0, v1);
        *(__half2*)&w.y = __floats2half2_rn(v2, v3);
        o[(size_t)node * SOUT4 + lane] = w;
    } else if (lane < SOUT4) {
        uint2 w;
        *(__half2*)&w.x = __floats2half2_rn(0.f, 0.f);
        *(__half2*)&w.y = __floats2half2_rn(0.f, 0.f);
        o[(size_t)node * SOUT4 + lane] = w;
    }
}

// ---------------- launch ----------------------------------------------------
extern "C" void kernel_launch(void* const* d_in, const int* in_sizes, int n_in,
                              void* d_out, int out_size) {
    const float* x  = (const float*)d_in[0];
    const float* W1 = (const float*)d_in[1];
    const float* b1 = (const float*)d_in[2];
    const float* W2 = (const float*)d_in[3];
    const float* b2 = (const float*)d_in[4];
    const float* W3 = (const float*)d_in[5];
    const float* b3 = (const float*)d_in[6];
    const float* W4 = (const float*)d_in[7];
    const float* b4 = (const float*)d_in[8];
    const int*   ei = (const int*)d_in[9];

    int N = in_sizes[0] / 88;
    int E = in_sizes[9] / 2;
    const int* src = ei;
    const int* dst = ei + E;
    float* out = (float*)d_out;

    __half *t1, *h1, *t2, *h2, *a3, *t3, *a4, *wh;
    float* dinv;
    int *cnt, *fill, *rowptr, *csr, *bsum;
    cudaGetSymbolAddress((void**)&t1, g_t1);
    cudaGetSymbolAddress((void**)&h1, g_h1);
    cudaGetSymbolAddress((void**)&t2, g_t2);
    cudaGetSymbolAddress((void**)&h2, g_h2);
    cudaGetSymbolAddress((void**)&a3, g_a3);
    cudaGetSymbolAddress((void**)&t3, g_t3);
    cudaGetSymbolAddress((void**)&a4, g_a4);
    cudaGetSymbolAddress((void**)&wh, g_wh);
    cudaGetSymbolAddress((void**)&dinv, g_dinv);
    cudaGetSymbolAddress((void**)&cnt, g_cnt);
    cudaGetSymbolAddress((void**)&fill, g_fill);
    cudaGetSymbolAddress((void**)&rowptr, g_rowptr);
    cudaGetSymbolAddress((void**)&csr, g_csr);
    cudaGetSymbolAddress((void**)&bsum, g_bsum);

    int aggBlocks = (N * 32 + 255) / 256;
    int gemmBlocks = (N + 255) / 256;
    int nb = (N + 1023) / 1024;

    // dynamic smem sizes (bytes)
    const int SM1 = (256 * 104 + 96 * 72) * 2;   // 67072
    const int SM2 = (256 * 88 + 80 * 56) * 2;    // 54016
    const int SM3 = (256 * 72 + 64 * 72) * 2;    // 46080
    const int SM4 = (256 * 88 + 80 * 88) * 2;    // 59136
    cudaFuncSetAttribute(k_gemm_tc<96, 72, 1, 0, 1, 1>,
                         cudaFuncAttributeMaxDynamicSharedMemorySize, SM1);
    cudaFuncSetAttribute(k_gemm_tc<80, 56, 0, 0, 1, 1>,
                         cudaFuncAttributeMaxDynamicSharedMemorySize, SM2);
    cudaFuncSetAttribute(k_gemm_tc<64, 72, 0, 1, 1, 1>,
                         cudaFuncAttributeMaxDynamicSharedMemorySize, SM3);
    cudaFuncSetAttribute(k_gemm_tc<80, 88, 0, 0, 0, 0>,
                         cudaFuncAttributeMaxDynamicSharedMemorySize, SM4);

    cudaMemsetAsync(cnt, 0, (size_t)N * sizeof(int));
    k_count<<<(E + 255) / 256, 256>>>(dst, E, cnt);
    k_dinv<<<(N + 255) / 256, 256>>>(cnt, dinv, N);
    k_prep_w<<<90, 256>>>(W1, W2, W3, W4, wh);

    // profiled slot #4: L1 tensor GEMM  t1 = dinv o (x@W1)
    k_gemm_tc<96, 72, 1, 0, 1, 1><<<gemmBlocks, 256, SM1>>>(
        (const void*)x, wh + WOFF1, nullptr, dinv, (void*)t1, 72, 65, N);

    // CSR build
    k_scan_block<<<nb, 1024>>>(cnt, N, rowptr + 1, bsum);
    k_scan_sums<<<1, 128>>>(bsum, nb);
    k_finalize<<<(N + 255) / 256, 256>>>(bsum, rowptr, fill, N);
    k_fill<<<(E + 255) / 256, 256>>>(src, dst, E, rowptr, fill, csr);

    // L1 agg: h1 = relu(di*S(t1) + b1)
    k_agg<17, 18, 20><<<aggBlocks, 256>>>((const uint2*)t1, (uint2*)h1,
                                          rowptr, csr, dinv, b1, 65, 1, 0, N);
    // L2: t2 = dinv o (h1@W2); h2 = dinv o (di*S(t2) + b2)
    k_gemm_tc<80, 56, 0, 0, 1, 1><<<gemmBlocks, 256, SM2>>>(
        (const void*)h1, wh + WOFF2, nullptr, dinv, (void*)t2, 56, 50, N);
    k_agg<13, 14, 14><<<aggBlocks, 256>>>((const uint2*)t2, (uint2*)h2,
                                          rowptr, csr, dinv, b2, 50, 0, 1, N);
    // L3: a3 = di*S(h2); t3 = dinv o relu(a3@W3 + b3)
    k_agg<13, 14, 16><<<aggBlocks, 256>>>((const uint2*)h2, (uint2*)a3,
                                          rowptr, csr, dinv, nullptr, 50, 0, 0, N);
    k_gemm_tc<64, 72, 0, 1, 1, 1><<<gemmBlocks, 256, SM3>>>(
        (const void*)a3, wh + WOFF3, b3, dinv, (void*)t3, 72, 65, N);
    // L4: a4 = di*S(t3); out = a4@W4 + b4
    k_agg<17, 18, 20><<<aggBlocks, 256>>>((const uint2*)t3, (uint2*)a4,
                                          rowptr, csr, dinv, nullptr, 65, 0, 0, N);
    k_gemm_tc<80, 88, 0, 0, 0, 0><<<gemmBlocks, 256, SM4>>>(
        (const void*)a4, wh + WOFF4, b4, nullptr, (void*)out, 88, 88, N);
}

// round 8
// speedup vs baseline: 1.6894x; 1.0212x over previous
#include <cuda_runtime.h>
#include <cuda_fp16.h>
#include <cstdint>
#include <math.h>

#define MAXN 100000
#define MAXE 1600000

// ---------------- scratch (device globals; no allocation allowed) ----------
__device__ __align__(16) __half g_t1[MAXN * 72];  // GEMM1 out (d=65)
__device__ __align__(16) __half g_h1[MAXN * 80];  // agg1 out  (d=65, Kp=80)
__device__ __align__(16) __half g_t2[MAXN * 56];  // GEMM2 out (d=50)
__device__ __align__(16) __half g_h2[MAXN * 56];  // agg2 out  (d=50)
__device__ __align__(16) __half g_a3[MAXN * 64];  // agg3 out  (d=50, Kp=64)
__device__ __align__(16) __half g_t3[MAXN * 72];  // GEMM3 out (d=65)
__device__ __align__(16) __half g_a4[MAXN * 80];  // agg4 out  (d=65, Kp=80)
__device__ __align__(16) __half g_wh[23040];      // packed fp16 weights
__device__ float g_dinv[MAXN];
__device__ int   g_cnt[MAXN];
__device__ int   g_fill[MAXN];
__device__ int   g_rowptr[MAXN + 1];
__device__ int   g_csr[MAXE];
__device__ int   g_bsum[128];

#define WOFF1 0
#define WOFF2 6912
#define WOFF3 11392
#define WOFF4 16000

// ---------------- CSR build ------------------------------------------------
__global__ void k_count(const int* __restrict__ dst, int E, int* __restrict__ cnt) {
    int e = blockIdx.x * blockDim.x + threadIdx.x;
    if (e < E) atomicAdd(&cnt[dst[e]], 1);
}

__global__ void k_scan_block(const int* __restrict__ cnt, int n,
                             int* __restrict__ incl, int* __restrict__ bsum) {
    __shared__ int sh[1024];
    int tid = threadIdx.x;
    int gid = blockIdx.x * 1024 + tid;
    int v = (gid < n) ? cnt[gid] : 0;
    sh[tid] = v;
    __syncthreads();
    for (int off = 1; off < 1024; off <<= 1) {
        int t = 0;
        if (tid >= off) t = sh[tid - off];
        __syncthreads();
        sh[tid] += t;
        __syncthreads();
    }
    if (gid < n) incl[gid] = sh[tid];
    if (tid == 1023) bsum[blockIdx.x] = sh[1023];
}

// fused: exclusive-scan the <=128 block sums in smem (per block), add offset
// to rowptr, compute dinv, zero fill cursor.
__global__ void k_finalize2(const int* __restrict__ bsum, int nb,
                            int* __restrict__ rowptr, const int* __restrict__ cnt,
                            float* __restrict__ dinv, int* __restrict__ fill, int n) {
    __shared__ int sh[128];
    int tid = threadIdx.x;
    if (tid < 128) sh[tid] = (tid < nb) ? bsum[tid] : 0;
    __syncthreads();
    if (tid == 0) {
        int acc = 0;
        for (int i = 0; i < nb; i++) { int v = sh[i]; sh[i] = acc; acc += v; }
    }
    __syncthreads();
    int i = blockIdx.x * blockDim.x + threadIdx.x;
    if (i < n) {
        rowptr[i + 1] += sh[i >> 10];
        dinv[i] = rsqrtf((float)(cnt[i] + 1));  // +1 self loop
        fill[i] = 0;
        if (i == 0) rowptr[0] = 0;
    }
}

__global__ void k_fill(const int* __restrict__ src, const int* __restrict__ dst, int E,
                       const int* __restrict__ rowptr, int* __restrict__ fill,
                       int* __restrict__ csr) {
    int e = blockIdx.x * blockDim.x + threadIdx.x;
    if (e < E) {
        int d = dst[e];
        int p = atomicAdd(&fill[d], 1);
        csr[rowptr[d] + p] = src[e];
    }
}

// ---------------- weight conversion (fp32 -> fp16, zero-padded) ------------
__global__ void k_prep_w(const float* __restrict__ W1, const float* __restrict__ W2,
                         const float* __restrict__ W3, const float* __restrict__ W4,
                         __half* __restrict__ o) {
    int i = blockIdx.x * blockDim.x + threadIdx.x;
    if (i < 6912) {                                    // W1 [88x65] -> [96x72]
        int kk = i / 72;
        int nn = i - kk * 72;
        o[WOFF1 + i] = __float2half((kk < 88 && nn < 65) ? W1[kk * 65 + nn] : 0.f);
    } else if (i < 11392) {                            // W2 [65x50] -> [80x56]
        int j = i - 6912;
        int kk = j / 56;
        int nn = j - kk * 56;
        o[WOFF2 + j] = __float2half((kk < 65 && nn < 50) ? W2[kk * 50 + nn] : 0.f);
    } else if (i < 16000) {                            // W3 [50x65] -> [64x72]
        int j = i - 11392;
        int kk = j / 72;
        int nn = j - kk * 72;
        o[WOFF3 + j] = __float2half((kk < 50 && nn < 65) ? W3[kk * 65 + nn] : 0.f);
    } else if (i < 23040) {                            // W4 [65x88] -> [80x88]
        int j = i - 16000;
        int kk = j / 88;
        int nn = j - kk * 88;
        o[WOFF4 + j] = __float2half((kk < 65 && nn < 88) ? W4[kk * 88 + nn] : 0.f);
    }
}

// ---------------- tensor-core GEMM helpers ---------------------------------
__device__ __forceinline__ void ldsm_x4(unsigned int& a0, unsigned int& a1,
                                        unsigned int& a2, unsigned int& a3,
                                        const __half* p) {
    unsigned int addr = (unsigned int)__cvta_generic_to_shared((const void*)p);
    asm volatile("ldmatrix.sync.aligned.m8n8.x4.shared.b16 {%0,%1,%2,%3}, [%4];"
                 : "=r"(a0), "=r"(a1), "=r"(a2), "=r"(a3)
                 : "r"(addr));
}

__device__ __forceinline__ void ldsm_x2t(unsigned int& b0, unsigned int& b1,
                                         const __half* p) {
    unsigned int addr = (unsigned int)__cvta_generic_to_shared((const void*)p);
    asm volatile("ldmatrix.sync.aligned.m8n8.x2.trans.shared.b16 {%0,%1}, [%2];"
                 : "=r"(b0), "=r"(b1)
                 : "r"(addr));
}

__device__ __forceinline__ void mma16816(float& d0, float& d1, float& d2, float& d3,
                                         unsigned int a0, unsigned int a1,
                                         unsigned int a2, unsigned int a3,
                                         unsigned int b0, unsigned int b1) {
    asm volatile("mma.sync.aligned.m16n8k16.row.col.f32.f16.f16.f32 "
                 "{%0,%1,%2,%3}, {%4,%5,%6,%7}, {%8,%9}, {%0,%1,%2,%3};"
                 : "+f"(d0), "+f"(d1), "+f"(d2), "+f"(d3)
                 : "r"(a0), "r"(a1), "r"(a2), "r"(a3), "r"(b0), "r"(b1));
}

// C[N, Np] = A[N, Kp] * B[Kp, Np]; block = 256 rows, 256 threads (8 warps).
template <int Kp, int Np, int AF32, int RELU, int SCALE, int OUT_HALF>
__global__ void __launch_bounds__(256)
k_gemm_tc(const void* Av,
          const __half* __restrict__ B,
          const float* __restrict__ bias,
          const float* __restrict__ dinv,
          void* Cv, int ldc, int M, int N) {
    const int KT = Kp / 16;
    const int NT = Np / 8;
    const int LDA = Kp + 8;
    const int LDB = Np;
    extern __shared__ char smem_raw[];
    __half* sA = (__half*)smem_raw;                 // 256 x LDA
    __half* sB = (__half*)smem_raw + 256 * LDA;     // Kp x LDB

    int tid = threadIdx.x;
    int warp = tid >> 5;
    int lane = tid & 31;
    int r0 = blockIdx.x * 256;

    if (AF32) {
        const float4* Ag = (const float4*)Av;       // 88 floats = 22 float4/row
        for (int i = tid; i < 256 * 22; i += 256) {
            int r = i / 22;
            int v = i - r * 22;
            int gr = r0 + r;
            float4 f = make_float4(0.f, 0.f, 0.f, 0.f);
            if (gr < N) f = Ag[(size_t)gr * 22 + v];
            __half2* p = (__half2*)&sA[r * LDA + v * 4];
            p[0] = __floats2half2_rn(f.x, f.y);
            p[1] = __floats2half2_rn(f.z, f.w);
        }
        for (int i = tid; i < 256 * 4; i += 256) {   // zero cols 88..95
            int r = i >> 2;
            int v = i & 3;
            *(__half2*)&sA[r * LDA + 88 + 2 * v] = __floats2half2_rn(0.f, 0.f);
        }
    } else {
        const int HV = Kp / 8;
        const uint4* Ag = (const uint4*)Av;
        for (int i = tid; i < 256 * HV; i += 256) {
            int r = i / HV;
            int v = i - r * HV;
            int gr = r0 + r;
            uint4 q = make_uint4(0u, 0u, 0u, 0u);
            if (gr < N) q = Ag[(size_t)gr * HV + v];
            *(uint4*)&sA[r * LDA + v * 8] = q;
        }
    }
    {
        const int BV = Np / 8;
        const uint4* Bg = (const uint4*)B;
        for (int i = tid; i < Kp * BV; i += 256) {
            int kk = i / BV;
            int v = i - kk * BV;
            *(uint4*)&sB[kk * LDB + v * 8] = Bg[i];
        }
    }
    __syncthreads();

    float acc0[NT][4];
    float acc1[NT][4];
#pragma unroll
    for (int nt = 0; nt < NT; nt++) {
#pragma unroll
        for (int q = 0; q < 4; q++) { acc0[nt][q] = 0.f; acc1[nt][q] = 0.f; }
    }

#pragma unroll
    for (int kt = 0; kt < KT; kt++) {
        unsigned int a0, a1, a2, a3, c0r, c1r, c2r, c3r;
        const __half* pa0 = &sA[(warp * 32 + (lane & 15)) * LDA + kt * 16 + (lane >> 4) * 8];
        const __half* pa1 = pa0 + 16 * LDA;
        ldsm_x4(a0, a1, a2, a3, pa0);
        ldsm_x4(c0r, c1r, c2r, c3r, pa1);
#pragma unroll
        for (int nt = 0; nt < NT; nt++) {
            unsigned int b0, b1;
            const __half* pb = &sB[(kt * 16 + (lane & 15)) * LDB + nt * 8];
            ldsm_x2t(b0, b1, pb);
            mma16816(acc0[nt][0], acc0[nt][1], acc0[nt][2], acc0[nt][3],
                     a0, a1, a2, a3, b0, b1);
            mma16816(acc1[nt][0], acc1[nt][1], acc1[nt][2], acc1[nt][3],
                     c0r, c1r, c2r, c3r, b0, b1);
        }
    }

    int rowA = r0 + warp * 32 + (lane >> 2);
    int colb = (lane & 3) * 2;
    float sc[4] = {1.f, 1.f, 1.f, 1.f};
    if (SCALE) {
#pragma unroll
        for (int t = 0; t < 4; t++) {
            int rr = rowA + t * 8;
            sc[t] = (rr < N) ? dinv[rr] : 0.f;
        }
    }
#pragma unroll
    for (int nt = 0; nt < NT; nt++) {
        int c0 = nt * 8 + colb;
        float b0v = 0.f;
        float b1v = 0.f;
        if (bias != nullptr) {
            b0v = (c0 < M) ? bias[c0] : 0.f;
            b1v = (c0 + 1 < M) ? bias[c0 + 1] : 0.f;
        }
        float vx[4], vy[4];
        vx[0] = acc0[nt][0]; vy[0] = acc0[nt][1];
        vx[1] = acc0[nt][2]; vy[1] = acc0[nt][3];
        vx[2] = acc1[nt][0]; vy[2] = acc1[nt][1];
        vx[3] = acc1[nt][2]; vy[3] = acc1[nt][3];
#pragma unroll
        for (int t = 0; t < 4; t++) {
            int rr = rowA + t * 8;
            if (rr >= N) continue;
            float v0 = vx[t] + b0v;
            float v1 = vy[t] + b1v;
            if (RELU) { v0 = fmaxf(v0, 0.f); v1 = fmaxf(v1, 0.f); }
            v0 *= sc[t]; v1 *= sc[t];
            if (c0 >= M)     v0 = 0.f;
            if (c0 + 1 >= M) v1 = 0.f;
            if (OUT_HALF) {
                __half* C = (__half*)Cv;
                *(__half2*)&C[(size_t)rr * ldc + c0] = __floats2half2_rn(v0, v1);
            } else {
                float* C = (float*)Cv;
                *(float2*)&C[(size_t)rr * ldc + c0] = make_float2(v0, v1);
            }
        }
    }
}

// ---------------- aggregation (uint2 fp16 gather, fp32 accumulate) ---------
// 8-edge software pipeline: 8 index loads, then 8 independent gathers in
// flight before accumulation (halves serialized L2 round-trips per node).
template <int D4, int SIN4, int SOUT4>
__global__ void k_agg(const uint2* __restrict__ t, uint2* __restrict__ o,
                      const int* __restrict__ rowptr, const int* __restrict__ csr,
                      const float* __restrict__ dinv,
                      const float* __restrict__ bias, int d,
                      int relu, int post2, int N) {
    int node = (blockIdx.x * blockDim.x + threadIdx.x) >> 5;
    int lane = threadIdx.x & 31;
    if (node >= N) return;
    int beg = rowptr[node];
    int end = rowptr[node + 1];
    bool act = (lane < D4);

    float a0 = 0.f, a1 = 0.f, a2 = 0.f, a3 = 0.f;

    int j = beg;
    for (; j + 8 <= end; j += 8) {
        int s[8];
#pragma unroll
        for (int k = 0; k < 8; k++) s[k] = __ldg(&csr[j + k]);
        if (act) {
            uint2 q[8];
#pragma unroll
            for (int k = 0; k < 8; k++) q[k] = __ldg(&t[(size_t)s[k] * SIN4 + lane]);
#pragma unroll
            for (int k = 0; k < 8; k++) {
                float2 f;
                f = __half22float2(*(__half2*)&q[k].x); a0 += f.x; a1 += f.y;
                f = __half22float2(*(__half2*)&q[k].y); a2 += f.x; a3 += f.y;
            }
        }
    }
    if (j + 4 <= end) {
        int s[4];
#pragma unroll
        for (int k = 0; k < 4; k++) s[k] = __ldg(&csr[j + k]);
        if (act) {
            uint2 q[4];
#pragma unroll
            for (int k = 0; k < 4; k++) q[k] = __ldg(&t[(size_t)s[k] * SIN4 + lane]);
#pragma unroll
            for (int k = 0; k < 4; k++) {
                float2 f;
                f = __half22float2(*(__half2*)&q[k].x); a0 += f.x; a1 += f.y;
                f = __half22float2(*(__half2*)&q[k].y); a2 += f.x; a3 += f.y;
            }
        }
        j += 4;
    }
    for (; j < end; j++) {
        int s0 = __ldg(&csr[j]);
        if (act) {
            uint2 q0 = __ldg(&t[(size_t)s0 * SIN4 + lane]);
            float2 f;
            f = __half22float2(*(__half2*)&q0.x); a0 += f.x; a1 += f.y;
            f = __half22float2(*(__half2*)&q0.y); a2 += f.x; a3 += f.y;
        }
    }
    // self loop (row already carries dinv_i)
    if (act) {
        uint2 q = __ldg(&t[(size_t)node * SIN4 + lane]);
        float2 f;
        f = __half22float2(*(__half2*)&q.x); a0 += f.x; a1 += f.y;
        f = __half22float2(*(__half2*)&q.y); a2 += f.x; a3 += f.y;
    }

    float di = dinv[node];
    if (act) {
        int c0 = 4 * lane;
        float v0 = a0 * di, v1 = a1 * di, v2 = a2 * di, v3 = a3 * di;
        if (bias != nullptr) {
            v0 += (c0 < d) ? bias[c0] : 0.f;
            v1 += (c0 + 1 < d) ? bias[c0 + 1] : 0.f;
            v2 += (c0 + 2 < d) ? bias[c0 + 2] : 0.f;
            v3 += (c0 + 3 < d) ? bias[c0 + 3] : 0.f;
        }
        if (relu) {
            v0 = fmaxf(v0, 0.f); v1 = fmaxf(v1, 0.f);
            v2 = fmaxf(v2, 0.f); v3 = fmaxf(v3, 0.f);
        }
        if (post2) { v0 *= di; v1 *= di; v2 *= di; v3 *= di; }
        if (c0 >= d)     v0 = 0.f;
        if (c0 + 1 >= d) v1 = 0.f;
        if (c0 + 2 >= d) v2 = 0.f;
        if (c0 + 3 >= d) v3 = 0.f;
        uint2 w;
        *(__half2*)&w.x = __floats2half2_rn(v0, v1);
        *(__half2*)&w.y = __floats2half2_rn(v2, v3);
        o[(size_t)node * SOUT4 + lane] = w;
    } else if (lane < SOUT4) {
        uint2 w;
        *(__half2*)&w.x = __floats2half2_rn(0.f, 0.f);
        *(__half2*)&w.y = __floats2half2_rn(0.f, 0.f);
        o[(size_t)node * SOUT4 + lane] = w;
    }
}

// ---------------- launch ----------------------------------------------------
extern "C" void kernel_launch(void* const* d_in, const int* in_sizes, int n_in,
                              void* d_out, int out_size) {
    const float* x  = (const float*)d_in[0];
    const float* W1 = (const float*)d_in[1];
    const float* b1 = (const float*)d_in[2];
    const float* W2 = (const float*)d_in[3];
    const float* b2 = (const float*)d_in[4];
    const float* W3 = (const float*)d_in[5];
    const float* b3 = (const float*)d_in[6];
    const float* W4 = (const float*)d_in[7];
    const float* b4 = (const float*)d_in[8];
    const int*   ei = (const int*)d_in[9];

    int N = in_sizes[0] / 88;
    int E = in_sizes[9] / 2;
    const int* src = ei;
    const int* dst = ei + E;
    float* out = (float*)d_out;

    __half *t1, *h1, *t2, *h2, *a3, *t3, *a4, *wh;
    float* dinv;
    int *cnt, *fill, *rowptr, *csr, *bsum;
    cudaGetSymbolAddress((void**)&t1, g_t1);
    cudaGetSymbolAddress((void**)&h1, g_h1);
    cudaGetSymbolAddress((void**)&t2, g_t2);
    cudaGetSymbolAddress((void**)&h2, g_h2);
    cudaGetSymbolAddress((void**)&a3, g_a3);
    cudaGetSymbolAddress((void**)&t3, g_t3);
    cudaGetSymbolAddress((void**)&a4, g_a4);
    cudaGetSymbolAddress((void**)&wh, g_wh);
    cudaGetSymbolAddress((void**)&dinv, g_dinv);
    cudaGetSymbolAddress((void**)&cnt, g_cnt);
    cudaGetSymbolAddress((void**)&fill, g_fill);
    cudaGetSymbolAddress((void**)&rowptr, g_rowptr);
    cudaGetSymbolAddress((void**)&csr, g_csr);
    cudaGetSymbolAddress((void**)&bsum, g_bsum);

    int aggBlocks = (N * 32 + 255) / 256;
    int gemmBlocks = (N + 255) / 256;
    int nb = (N + 1023) / 1024;

    const int SM1 = (256 * 104 + 96 * 72) * 2;   // 67072
    const int SM2 = (256 * 88 + 80 * 56) * 2;    // 54016
    const int SM3 = (256 * 72 + 64 * 72) * 2;    // 46080
    const int SM4 = (256 * 88 + 80 * 88) * 2;    // 59136
    cudaFuncSetAttribute(k_gemm_tc<96, 72, 1, 0, 1, 1>,
                         cudaFuncAttributeMaxDynamicSharedMemorySize, SM1);
    cudaFuncSetAttribute(k_gemm_tc<80, 56, 0, 0, 1, 1>,
                         cudaFuncAttributeMaxDynamicSharedMemorySize, SM2);
    cudaFuncSetAttribute(k_gemm_tc<64, 72, 0, 1, 1, 1>,
                         cudaFuncAttributeMaxDynamicSharedMemorySize, SM3);
    cudaFuncSetAttribute(k_gemm_tc<80, 88, 0, 0, 0, 0>,
                         cudaFuncAttributeMaxDynamicSharedMemorySize, SM4);

    cudaMemsetAsync(cnt, 0, (size_t)N * sizeof(int));
    // kernel launches 1..3
    k_count<<<(E + 255) / 256, 256>>>(dst, E, cnt);
    k_scan_block<<<nb, 1024>>>(cnt, N, rowptr + 1, bsum);
    k_finalize2<<<(N + 255) / 256, 256>>>(bsum, nb, rowptr, cnt, dinv, fill, N);
    // launch 4 <- profiled slot: CSR fill (atomic cursor + scatter)
    k_fill<<<(E + 255) / 256, 256>>>(src, dst, E, rowptr, fill, csr);

    k_prep_w<<<90, 256>>>(W1, W2, W3, W4, wh);

    // L1: t1 = dinv o (x@W1); h1 = relu(di*S(t1) + b1)
    k_gemm_tc<96, 72, 1, 0, 1, 1><<<gemmBlocks, 256, SM1>>>(
        (const void*)x, wh + WOFF1, nullptr, dinv, (void*)t1, 72, 65, N);
    k_agg<17, 18, 20><<<aggBlocks, 256>>>((const uint2*)t1, (uint2*)h1,
                                          rowptr, csr, dinv, b1, 65, 1, 0, N);
    // L2: t2 = dinv o (h1@W2); h2 = dinv o (di*S(t2) + b2)
    k_gemm_tc<80, 56, 0, 0, 1, 1><<<gemmBlocks, 256, SM2>>>(
        (const void*)h1, wh + WOFF2, nullptr, dinv, (void*)t2, 56, 50, N);
    k_agg<13, 14, 14><<<aggBlocks, 256>>>((const uint2*)t2, (uint2*)h2,
                                          rowptr, csr, dinv, b2, 50, 0, 1, N);
    // L3: a3 = di*S(h2); t3 = dinv o relu(a3@W3 + b3)
    k_agg<13, 14, 16><<<aggBlocks, 256>>>((const uint2*)h2, (uint2*)a3,
                                          rowptr, csr, dinv, nullptr, 50, 0, 0, N);
    k_gemm_tc<64, 72, 0, 1, 1, 1><<<gemmBlocks, 256, SM3>>>(
        (const void*)a3, wh + WOFF3, b3, dinv, (void*)t3, 72, 65, N);
    // L4: a4 = di*S(t3); out = a4@W4 + b4
    k_agg<17, 18, 20><<<aggBlocks, 256>>>((const uint2*)t3, (uint2*)a4,
                                          rowptr, csr, dinv, nullptr, 65, 0, 0, N);
    k_gemm_tc<80, 88, 0, 0, 0, 0><<<gemmBlocks, 256, SM4>>>(
        (const void*)a4, wh + WOFF4, b4, nullptr, (void*)out, 88, 88, N);
}

// round 9
// speedup vs baseline: 1.7266x; 1.0220x over previous
#include <cuda_runtime.h>
#include <cuda_fp16.h>
#include <cstdint>
#include <math.h>

#define MAXN 100000
#define MAXE 1600000

// ---------------- scratch (device globals; no allocation allowed) ----------
__device__ __align__(16) __half g_t1[MAXN * 72];  // GEMM1 out (d=65)
__device__ __align__(16) __half g_h1[MAXN * 80];  // agg1 out  (d=65, Kp=80)
__device__ __align__(16) __half g_t2[MAXN * 56];  // GEMM2 out (d=50)
__device__ __align__(16) __half g_h2[MAXN * 56];  // agg2 out  (d=50)
__device__ __align__(16) __half g_a3[MAXN * 64];  // agg3 out  (d=50, Kp=64)
__device__ __align__(16) __half g_t3[MAXN * 72];  // GEMM3 out (d=65)
__device__ __align__(16) __half g_a4[MAXN * 80];  // agg4 out  (d=65, Kp=80)
__device__ __align__(16) __half g_wh[23040];      // packed fp16 weights
__device__ float g_dinv[MAXN];
__device__ int   g_cnt[MAXN];
__device__ int   g_fill[MAXN];
__device__ int   g_rowptr[MAXN + 1];
__device__ int   g_csr[MAXE];
__device__ int   g_bsum[128];

#define WOFF1 0
#define WOFF2 6912
#define WOFF3 11392
#define WOFF4 16000

// ---------------- CSR build ------------------------------------------------
__global__ void k_count(const int* __restrict__ dst, int E, int* __restrict__ cnt) {
    int e = blockIdx.x * blockDim.x + threadIdx.x;
    if (e < E) atomicAdd(&cnt[dst[e]], 1);
}

__global__ void k_scan_block(const int* __restrict__ cnt, int n,
                             int* __restrict__ incl, int* __restrict__ bsum) {
    __shared__ int sh[1024];
    int tid = threadIdx.x;
    int gid = blockIdx.x * 1024 + tid;
    int v = (gid < n) ? cnt[gid] : 0;
    sh[tid] = v;
    __syncthreads();
    for (int off = 1; off < 1024; off <<= 1) {
        int t = 0;
        if (tid >= off) t = sh[tid - off];
        __syncthreads();
        sh[tid] += t;
        __syncthreads();
    }
    if (gid < n) incl[gid] = sh[tid];
    if (tid == 1023) bsum[blockIdx.x] = sh[1023];
}

// fused: scan the <=128 block sums (per block, in smem), add offset to rowptr,
// compute dinv, init fill cursor to the row START (exclusive prefix).
__global__ void k_finalize2(const int* __restrict__ bsum, int nb,
                            int* __restrict__ rowptr, const int* __restrict__ cnt,
                            float* __restrict__ dinv, int* __restrict__ fill, int n) {
    __shared__ int sh[128];
    int tid = threadIdx.x;
    if (tid < 128) sh[tid] = (tid < nb) ? bsum[tid] : 0;
    __syncthreads();
    if (tid == 0) {
        int acc = 0;
        for (int i = 0; i < nb; i++) { int v = sh[i]; sh[i] = acc; acc += v; }
    }
    __syncthreads();
    int i = blockIdx.x * blockDim.x + threadIdx.x;
    if (i < n) {
        int c = cnt[i];
        int r1 = rowptr[i + 1] + sh[i >> 10];
        rowptr[i + 1] = r1;
        fill[i] = r1 - c;                       // row start = cursor init
        dinv[i] = rsqrtf((float)(c + 1));       // +1 self loop
        if (i == 0) rowptr[0] = 0;
    }
}

__global__ void k_fill(const int* __restrict__ src, const int* __restrict__ dst, int E,
                       int* __restrict__ fill, int* __restrict__ csr) {
    int e = blockIdx.x * blockDim.x + threadIdx.x;
    if (e < E) {
        int p = atomicAdd(&fill[dst[e]], 1);
        csr[p] = src[e];
    }
}

// ---------------- weight conversion (fp32 -> fp16, zero-padded) ------------
__global__ void k_prep_w(const float* __restrict__ W1, const float* __restrict__ W2,
                         const float* __restrict__ W3, const float* __restrict__ W4,
                         __half* __restrict__ o) {
    int i = blockIdx.x * blockDim.x + threadIdx.x;
    if (i < 6912) {                                    // W1 [88x65] -> [96x72]
        int kk = i / 72;
        int nn = i - kk * 72;
        o[WOFF1 + i] = __float2half((kk < 88 && nn < 65) ? W1[kk * 65 + nn] : 0.f);
    } else if (i < 11392) {                            // W2 [65x50] -> [80x56]
        int j = i - 6912;
        int kk = j / 56;
        int nn = j - kk * 56;
        o[WOFF2 + j] = __float2half((kk < 65 && nn < 50) ? W2[kk * 50 + nn] : 0.f);
    } else if (i < 16000) {                            // W3 [50x65] -> [64x72]
        int j = i - 11392;
        int kk = j / 72;
        int nn = j - kk * 72;
        o[WOFF3 + j] = __float2half((kk < 50 && nn < 65) ? W3[kk * 65 + nn] : 0.f);
    } else if (i < 23040) {                            // W4 [65x88] -> [80x88]
        int j = i - 16000;
        int kk = j / 88;
        int nn = j - kk * 88;
        o[WOFF4 + j] = __float2half((kk < 65 && nn < 88) ? W4[kk * 88 + nn] : 0.f);
    }
}

// ---------------- tensor-core GEMM helpers ---------------------------------
__device__ __forceinline__ void ldsm_x4(unsigned int& a0, unsigned int& a1,
                                        unsigned int& a2, unsigned int& a3,
                                        const __half* p) {
    unsigned int addr = (unsigned int)__cvta_generic_to_shared((const void*)p);
    asm volatile("ldmatrix.sync.aligned.m8n8.x4.shared.b16 {%0,%1,%2,%3}, [%4];"
                 : "=r"(a0), "=r"(a1), "=r"(a2), "=r"(a3)
                 : "r"(addr));
}

__device__ __forceinline__ void ldsm_x2t(unsigned int& b0, unsigned int& b1,
                                         const __half* p) {
    unsigned int addr = (unsigned int)__cvta_generic_to_shared((const void*)p);
    asm volatile("ldmatrix.sync.aligned.m8n8.x2.trans.shared.b16 {%0,%1}, [%2];"
                 : "=r"(b0), "=r"(b1)
                 : "r"(addr));
}

__device__ __forceinline__ void mma16816(float& d0, float& d1, float& d2, float& d3,
                                         unsigned int a0, unsigned int a1,
                                         unsigned int a2, unsigned int a3,
                                         unsigned int b0, unsigned int b1) {
    asm volatile("mma.sync.aligned.m16n8k16.row.col.f32.f16.f16.f32 "
                 "{%0,%1,%2,%3}, {%4,%5,%6,%7}, {%8,%9}, {%0,%1,%2,%3};"
                 : "+f"(d0), "+f"(d1), "+f"(d2), "+f"(d3)
                 : "r"(a0), "r"(a1), "r"(a2), "r"(a3), "r"(b0), "r"(b1));
}

// C[N, Np] = A[N, Kp] * B[Kp, Np]; block = 128 rows, 256 threads (8 warps),
// warp owns 16 rows. LDA = Kp+8, LDB = Np (both conflict-free for ldmatrix).
template <int Kp, int Np, int AF32, int RELU, int SCALE, int OUT_HALF>
__global__ void __launch_bounds__(256)
k_gemm_tc(const void* Av,
          const __half* __restrict__ B,
          const float* __restrict__ bias,
          const float* __restrict__ dinv,
          void* Cv, int ldc, int M, int N) {
    const int KT = Kp / 16;
    const int NT = Np / 8;
    const int LDA = Kp + 8;
    const int LDB = Np;
    extern __shared__ char smem_raw[];
    __half* sA = (__half*)smem_raw;                 // 128 x LDA
    __half* sB = (__half*)smem_raw + 128 * LDA;     // Kp x LDB

    int tid = threadIdx.x;
    int warp = tid >> 5;
    int lane = tid & 31;
    int r0 = blockIdx.x * 128;

    if (AF32) {
        const float4* Ag = (const float4*)Av;       // 88 floats = 22 float4/row
        for (int i = tid; i < 128 * 22; i += 256) {
            int r = i / 22;
            int v = i - r * 22;
            int gr = r0 + r;
            float4 f = make_float4(0.f, 0.f, 0.f, 0.f);
            if (gr < N) f = Ag[(size_t)gr * 22 + v];
            __half2* p = (__half2*)&sA[r * LDA + v * 4];
            p[0] = __floats2half2_rn(f.x, f.y);
            p[1] = __floats2half2_rn(f.z, f.w);
        }
        for (int i = tid; i < 128 * 4; i += 256) {   // zero cols 88..95
            int r = i >> 2;
            int v = i & 3;
            *(__half2*)&sA[r * LDA + 88 + 2 * v] = __floats2half2_rn(0.f, 0.f);
        }
    } else {
        const int HV = Kp / 8;
        const uint4* Ag = (const uint4*)Av;
        for (int i = tid; i < 128 * HV; i += 256) {
            int r = i / HV;
            int v = i - r * HV;
            int gr = r0 + r;
            uint4 q = make_uint4(0u, 0u, 0u, 0u);
            if (gr < N) q = Ag[(size_t)gr * HV + v];
            *(uint4*)&sA[r * LDA + v * 8] = q;
        }
    }
    {
        const int BV = Np / 8;
        const uint4* Bg = (const uint4*)B;
        for (int i = tid; i < Kp * BV; i += 256) {
            int kk = i / BV;
            int v = i - kk * BV;
            *(uint4*)&sB[kk * LDB + v * 8] = Bg[i];
        }
    }
    __syncthreads();

    float acc[NT][4];
#pragma unroll
    for (int nt = 0; nt < NT; nt++) {
#pragma unroll
        for (int q = 0; q < 4; q++) acc[nt][q] = 0.f;
    }

#pragma unroll
    for (int kt = 0; kt < KT; kt++) {
        unsigned int a0, a1, a2, a3;
        const __half* pa = &sA[(warp * 16 + (lane & 15)) * LDA + kt * 16 + (lane >> 4) * 8];
        ldsm_x4(a0, a1, a2, a3, pa);
#pragma unroll
        for (int nt = 0; nt < NT; nt++) {
            unsigned int b0, b1;
            const __half* pb = &sB[(kt * 16 + (lane & 15)) * LDB + nt * 8];
            ldsm_x2t(b0, b1, pb);
            mma16816(acc[nt][0], acc[nt][1], acc[nt][2], acc[nt][3],
                     a0, a1, a2, a3, b0, b1);
        }
    }

    int row = r0 + warp * 16 + (lane >> 2);
    int colb = (lane & 3) * 2;
    float sc0 = 1.f;
    float sc1 = 1.f;
    if (SCALE) {
        sc0 = (row < N) ? dinv[row] : 0.f;
        sc1 = (row + 8 < N) ? dinv[row + 8] : 0.f;
    }
#pragma unroll
    for (int nt = 0; nt < NT; nt++) {
        int c0 = nt * 8 + colb;
        float b0v = 0.f;
        float b1v = 0.f;
        if (bias != nullptr) {
            b0v = (c0 < M) ? bias[c0] : 0.f;
            b1v = (c0 + 1 < M) ? bias[c0 + 1] : 0.f;
        }
        float v00 = acc[nt][0] + b0v;
        float v01 = acc[nt][1] + b1v;
        float v10 = acc[nt][2] + b0v;
        float v11 = acc[nt][3] + b1v;
        if (RELU) {
            v00 = fmaxf(v00, 0.f); v01 = fmaxf(v01, 0.f);
            v10 = fmaxf(v10, 0.f); v11 = fmaxf(v11, 0.f);
        }
        v00 *= sc0; v01 *= sc0; v10 *= sc1; v11 *= sc1;
        if (c0 >= M)     { v00 = 0.f; v10 = 0.f; }
        if (c0 + 1 >= M) { v01 = 0.f; v11 = 0.f; }
        if (OUT_HALF) {
            __half* C = (__half*)Cv;
            if (row < N)
                *(__half2*)&C[(size_t)row * ldc + c0] = __floats2half2_rn(v00, v01);
            if (row + 8 < N)
                *(__half2*)&C[(size_t)(row + 8) * ldc + c0] = __floats2half2_rn(v10, v11);
        } else {
            float* C = (float*)Cv;
            if (row < N)
                *(float2*)&C[(size_t)row * ldc + c0] = make_float2(v00, v01);
            if (row + 8 < N)
                *(float2*)&C[(size_t)(row + 8) * ldc + c0] = make_float2(v10, v11);
        }
    }
}

// ---------------- aggregation: 2 edges / gather instruction -----------------
// uint4 (8-half) granularity. Lanes 0..LPE-1 gather edge A, lanes 16..16+LPE-1
// gather edge B; shfl_xor(16) reduces the pair. LPE=9 (d=65) / 7 (d=50).
// SIN/SOUT = row strides in uint4 units. Output pads (cols>=D) written zero.
__device__ __forceinline__ void add8(float* acc, uint4 q) {
    float2 f;
    f = __half22float2(*(__half2*)&q.x); acc[0] += f.x; acc[1] += f.y;
    f = __half22float2(*(__half2*)&q.y); acc[2] += f.x; acc[3] += f.y;
    f = __half22float2(*(__half2*)&q.z); acc[4] += f.x; acc[5] += f.y;
    f = __half22float2(*(__half2*)&q.w); acc[6] += f.x; acc[7] += f.y;
}

template <int LPE, int SIN, int SOUT, int D>
__global__ void k_agg(const uint4* __restrict__ t, uint4* __restrict__ o,
                      const int* __restrict__ rowptr, const int* __restrict__ csr,
                      const float* __restrict__ dinv,
                      const float* __restrict__ bias,
                      int relu, int post2, int N) {
    int node = (blockIdx.x * blockDim.x + threadIdx.x) >> 5;
    int lane = threadIdx.x & 31;
    if (node >= N) return;
    int sub = lane >> 4;      // 0: edge j, 1: edge j+1
    int ln = lane & 15;       // uint4 index within row
    bool act = ln < LPE;
    int beg = rowptr[node];
    int end = rowptr[node + 1];

    float acc[8];
#pragma unroll
    for (int k = 0; k < 8; k++) acc[k] = 0.f;
    const uint4 z4 = make_uint4(0u, 0u, 0u, 0u);

    int j = beg;
    for (; j + 8 <= end; j += 8) {
        int s0 = __ldg(&csr[j + sub]);
        int s1 = __ldg(&csr[j + 2 + sub]);
        int s2 = __ldg(&csr[j + 4 + sub]);
        int s3 = __ldg(&csr[j + 6 + sub]);
        uint4 q0 = act ? __ldg(&t[(size_t)s0 * SIN + ln]) : z4;
        uint4 q1 = act ? __ldg(&t[(size_t)s1 * SIN + ln]) : z4;
        uint4 q2 = act ? __ldg(&t[(size_t)s2 * SIN + ln]) : z4;
        uint4 q3 = act ? __ldg(&t[(size_t)s3 * SIN + ln]) : z4;
        add8(acc, q0); add8(acc, q1); add8(acc, q2); add8(acc, q3);
    }
    for (; j + 2 <= end; j += 2) {
        int s0 = __ldg(&csr[j + sub]);
        uint4 q0 = act ? __ldg(&t[(size_t)s0 * SIN + ln]) : z4;
        add8(acc, q0);
    }
    if (j < end) {   // odd leftover edge: sub==0 half handles it
        int s0 = __ldg(&csr[j]);
        uint4 q0 = (act && sub == 0) ? __ldg(&t[(size_t)s0 * SIN + ln]) : z4;
        add8(acc, q0);
    }
    // self loop (row already carries dinv_i): sub==0 half only
    {
        uint4 q = (act && sub == 0) ? __ldg(&t[(size_t)node * SIN + ln]) : z4;
        add8(acc, q);
    }

#pragma unroll
    for (int k = 0; k < 8; k++)
        acc[k] += __shfl_xor_sync(0xFFFFFFFFu, acc[k], 16);

    if (sub == 0 && ln < SOUT) {
        float di = dinv[node];
        uint4 w;
        __half2* wh2 = (__half2*)&w;
#pragma unroll
        for (int p = 0; p < 4; p++) {
            int c0 = 8 * ln + 2 * p;
            float v0 = acc[2 * p] * di;
            float v1 = acc[2 * p + 1] * di;
            if (bias != nullptr) {
                v0 += (c0 < D) ? bias[c0] : 0.f;
                v1 += (c0 + 1 < D) ? bias[c0 + 1] : 0.f;
            }
            if (relu) { v0 = fmaxf(v0, 0.f); v1 = fmaxf(v1, 0.f); }
            if (post2) { v0 *= di; v1 *= di; }
            if (c0 >= D) v0 = 0.f;
            if (c0 + 1 >= D) v1 = 0.f;
            wh2[p] = __floats2half2_rn(v0, v1);
        }
        o[(size_t)node * SOUT + ln] = w;
    }
}

// ---------------- launch ----------------------------------------------------
extern "C" void kernel_launch(void* const* d_in, const int* in_sizes, int n_in,
                              void* d_out, int out_size) {
    const float* x  = (const float*)d_in[0];
    const float* W1 = (const float*)d_in[1];
    const float* b1 = (const float*)d_in[2];
    const float* W2 = (const float*)d_in[3];
    const float* b2 = (const float*)d_in[4];
    const float* W3 = (const float*)d_in[5];
    const float* b3 = (const float*)d_in[6];
    const float* W4 = (const float*)d_in[7];
    const float* b4 = (const float*)d_in[8];
    const int*   ei = (const int*)d_in[9];

    int N = in_sizes[0] / 88;
    int E = in_sizes[9] / 2;
    const int* src = ei;
    const int* dst = ei + E;
    float* out = (float*)d_out;

    __half *t1, *h1, *t2, *h2, *a3, *t3, *a4, *wh;
    float* dinv;
    int *cnt, *fill, *rowptr, *csr, *bsum;
    cudaGetSymbolAddress((void**)&t1, g_t1);
    cudaGetSymbolAddress((void**)&h1, g_h1);
    cudaGetSymbolAddress((void**)&t2, g_t2);
    cudaGetSymbolAddress((void**)&h2, g_h2);
    cudaGetSymbolAddress((void**)&a3, g_a3);
    cudaGetSymbolAddress((void**)&t3, g_t3);
    cudaGetSymbolAddress((void**)&a4, g_a4);
    cudaGetSymbolAddress((void**)&wh, g_wh);
    cudaGetSymbolAddress((void**)&dinv, g_dinv);
    cudaGetSymbolAddress((void**)&cnt, g_cnt);
    cudaGetSymbolAddress((void**)&fill, g_fill);
    cudaGetSymbolAddress((void**)&rowptr, g_rowptr);
    cudaGetSymbolAddress((void**)&csr, g_csr);
    cudaGetSymbolAddress((void**)&bsum, g_bsum);

    int aggBlocks = (N * 32 + 255) / 256;
    int gemmBlocks = (N + 127) / 128;
    int nb = (N + 1023) / 1024;

    const int SM1 = (128 * 104 + 96 * 72) * 2;   // 40448
    const int SM2 = (128 * 88 + 80 * 56) * 2;    // 31488
    const int SM3 = (128 * 72 + 64 * 72) * 2;    // 27648
    const int SM4 = (128 * 88 + 80 * 88) * 2;    // 36608
    cudaFuncSetAttribute(k_gemm_tc<96, 72, 1, 0, 1, 1>,
                         cudaFuncAttributeMaxDynamicSharedMemorySize, SM1);
    cudaFuncSetAttribute(k_gemm_tc<80, 56, 0, 0, 1, 1>,
                         cudaFuncAttributeMaxDynamicSharedMemorySize, SM2);
    cudaFuncSetAttribute(k_gemm_tc<64, 72, 0, 1, 1, 1>,
                         cudaFuncAttributeMaxDynamicSharedMemorySize, SM3);
    cudaFuncSetAttribute(k_gemm_tc<80, 88, 0, 0, 0, 0>,
                         cudaFuncAttributeMaxDynamicSharedMemorySize, SM4);

    cudaMemsetAsync(cnt, 0, (size_t)N * sizeof(int));
    // kernel launches 1..3
    k_count<<<(E + 255) / 256, 256>>>(dst, E, cnt);
    k_scan_block<<<nb, 1024>>>(cnt, N, rowptr + 1, bsum);
    k_finalize2<<<(N + 255) / 256, 256>>>(bsum, nb, rowptr, cnt, dinv, fill, N);
    // launch 4 <- profiled slot: CSR fill (cursor atomics, no rowptr gather)
    k_fill<<<(E + 255) / 256, 256>>>(src, dst, E, fill, csr);

    k_prep_w<<<90, 256>>>(W1, W2, W3, W4, wh);

    // L1: t1 = dinv o (x@W1); h1 = relu(di*S(t1) + b1)
    k_gemm_tc<96, 72, 1, 0, 1, 1><<<gemmBlocks, 256, SM1>>>(
        (const void*)x, wh + WOFF1, nullptr, dinv, (void*)t1, 72, 65, N);
    k_agg<9, 9, 10, 65><<<aggBlocks, 256>>>((const uint4*)t1, (uint4*)h1,
                                            rowptr, csr, dinv, b1, 1, 0, N);
    // L2: t2 = dinv o (h1@W2); h2 = dinv o (di*S(t2) + b2)
    k_gemm_tc<80, 56, 0, 0, 1, 1><<<gemmBlocks, 256, SM2>>>(
        (const void*)h1, wh + WOFF2, nullptr, dinv, (void*)t2, 56, 50, N);
    k_agg<7, 7, 7, 50><<<aggBlocks, 256>>>((const uint4*)t2, (uint4*)h2,
                                           rowptr, csr, dinv, b2, 0, 1, N);
    // L3: a3 = di*S(h2); t3 = dinv o relu(a3@W3 + b3)
    k_agg<7, 7, 8, 50><<<aggBlocks, 256>>>((const uint4*)h2, (uint4*)a3,
                                           rowptr, csr, dinv, nullptr, 0, 0, N);
    k_gemm_tc<64, 72, 0, 1, 1, 1><<<gemmBlocks, 256, SM3>>>(
        (const void*)a3, wh + WOFF3, b3, dinv, (void*)t3, 72, 65, N);
    // L4: a4 = di*S(t3); out = a4@W4 + b4
    k_agg<9, 9, 10, 65><<<aggBlocks, 256>>>((const uint4*)t3, (uint4*)a4,
                                            rowptr, csr, dinv, nullptr, 0, 0, N);
    k_gemm_tc<80, 88, 0, 0, 0, 0><<<gemmBlocks, 256, SM4>>>(
        (const void*)a4, wh + WOFF4, b4, nullptr, (void*)out, 88, 88, N);
}